// round 2
// baseline (speedup 1.0000x reference)
#include <cuda_runtime.h>
#include <math.h>
#include <stdint.h>

// Problem constants
#define BB 8
#define LL 1024
#define DD 512
#define HH 8
#define DHD 64
#define SS 1024
#define SCALE 0.125f

// Output section offsets (floats) in d_out: out_re | out_im | attn_re | attn_im
#define OUT_RE_OFF  0UL
#define OUT_IM_OFF  4194304UL
#define ATTN_RE_OFF 8388608UL
#define ATTN_IM_OFF 16777216UL

// Scratch: scaled scores, overwritten in-place by softmax probabilities.
// [B,H,L,S] each = 64M floats = 256 MB.  (__device__ BSS: allowed scratch.)
__device__ float g_sre[(size_t)BB * HH * LL * SS];
__device__ float g_sim[(size_t)BB * HH * LL * SS];

// ---------------------------------------------------------------------------
// K1: scores.  s_re = Qr Qr^T - Qi Qi^T,  s_im = Qr Qi^T + Qi Qr^T, scaled.
// Tile: 128 (l) x 64 (s), K = Dh = 64 fully resident.
// 256 threads, each computes an 8x4 micro-tile of (re,im) pairs.
// Q tiles stored [row][d] pad-65 (scalar broadcast reads);
// K tiles stored transposed [d][col] with XOR swizzle (conflict-free float4).
// ---------------------------------------------------------------------------
__global__ void __launch_bounds__(256, 2) k_scores(
    const float* __restrict__ xre, const float* __restrict__ xim)
{
    extern __shared__ float sm[];
    float* qre = sm;                 // [128][65]
    float* qim = qre + 128 * 65;     // [128][65]
    float* kre = qim + 128 * 65;     // [64][64] swizzled
    float* kim = kre + 64 * 64;      // [64][64] swizzled

    const int bh = blockIdx.z;
    const int b = bh >> 3, h = bh & 7;
    const int l0 = blockIdx.y << 7;
    const int s0 = blockIdx.x << 6;
    const int tid = threadIdx.x;

    const float* xr = xre + (size_t)b * LL * DD + h * DHD;
    const float* xi = xim + (size_t)b * LL * DD + h * DHD;

    // Load Q tile: 128 rows x 64 d, coalesced global, conflict-free STS
    #pragma unroll
    for (int i = 0; i < 32; i++) {
        int idx = tid + (i << 8);
        int row = idx >> 6, d = idx & 63;
        size_t g = (size_t)(l0 + row) * DD + d;
        qre[row * 65 + d] = xr[g];
        qim[row * 65 + d] = xi[g];
    }
    // Load K tile transposed with swizzle: (col,d) -> d*64 + 4*((col>>2)^(d&15)) + (col&3)
    #pragma unroll
    for (int i = 0; i < 16; i++) {
        int idx = tid + (i << 8);
        int col = idx >> 6, d = idx & 63;
        int soff = (d << 6) + ((((col >> 2) ^ (d & 15))) << 2) + (col & 3);
        size_t g = (size_t)(s0 + col) * DD + d;
        kre[soff] = xr[g];
        kim[soff] = xi[g];
    }
    __syncthreads();

    const int tx = tid & 15, ty = tid >> 4;
    const float* qrb = qre + ty * 8 * 65;
    const float* qib = qim + ty * 8 * 65;

    float are[8][4], aim[8][4];
    #pragma unroll
    for (int r = 0; r < 8; r++)
        #pragma unroll
        for (int c = 0; c < 4; c++) { are[r][c] = 0.f; aim[r][c] = 0.f; }

    for (int d = 0; d < 64; d++) {
        int ko = (d << 6) + ((tx ^ (d & 15)) << 2);
        float4 krv = *(const float4*)(kre + ko);
        float4 kiv = *(const float4*)(kim + ko);
        float kra[4] = { krv.x, krv.y, krv.z, krv.w };
        float kia[4] = { kiv.x, kiv.y, kiv.z, kiv.w };
        #pragma unroll
        for (int r = 0; r < 8; r++) {
            float qr = qrb[r * 65 + d];
            float qi = qib[r * 65 + d];
            #pragma unroll
            for (int c = 0; c < 4; c++) {
                are[r][c] = fmaf(qr, kra[c], fmaf(-qi, kia[c], are[r][c]));
                aim[r][c] = fmaf(qr, kia[c], fmaf( qi, kra[c], aim[r][c]));
            }
        }
    }

    // Write scaled scores (float4, coalesced)
    float* pre = g_sre + ((size_t)bh * LL + (l0 + ty * 8)) * SS + s0 + (tx << 2);
    float* pim = g_sim + ((size_t)bh * LL + (l0 + ty * 8)) * SS + s0 + (tx << 2);
    #pragma unroll
    for (int r = 0; r < 8; r++) {
        float4 vr = make_float4(are[r][0] * SCALE, are[r][1] * SCALE,
                                are[r][2] * SCALE, are[r][3] * SCALE);
        float4 vi = make_float4(aim[r][0] * SCALE, aim[r][1] * SCALE,
                                aim[r][2] * SCALE, aim[r][3] * SCALE);
        *(float4*)(pre + (size_t)r * SS) = vr;
        *(float4*)(pim + (size_t)r * SS) = vi;
    }
}

// ---------------------------------------------------------------------------
// Block-wide reductions (256 threads = 8 warps)
// ---------------------------------------------------------------------------
__device__ __forceinline__ float block_max(float v, float* red) {
    #pragma unroll
    for (int o = 16; o; o >>= 1) v = fmaxf(v, __shfl_xor_sync(0xffffffffu, v, o));
    int w = threadIdx.x >> 5, lane = threadIdx.x & 31;
    if (lane == 0) red[w] = v;
    __syncthreads();
    if (w == 0) {
        float x = (lane < 8) ? red[lane] : -3.4e38f;
        #pragma unroll
        for (int o = 4; o; o >>= 1) x = fmaxf(x, __shfl_xor_sync(0xffffffffu, x, o));
        if (lane == 0) red[0] = x;
    }
    __syncthreads();
    float r = red[0];
    __syncthreads();
    return r;
}

__device__ __forceinline__ float block_sum(float v, float* red) {
    #pragma unroll
    for (int o = 16; o; o >>= 1) v += __shfl_xor_sync(0xffffffffu, v, o);
    int w = threadIdx.x >> 5, lane = threadIdx.x & 31;
    if (lane == 0) red[w] = v;
    __syncthreads();
    if (w == 0) {
        float x = (lane < 8) ? red[lane] : 0.f;
        #pragma unroll
        for (int o = 4; o; o >>= 1) x += __shfl_xor_sync(0xffffffffu, x, o);
        if (lane == 0) red[0] = x;
    }
    __syncthreads();
    float r = red[0];
    __syncthreads();
    return r;
}

// ---------------------------------------------------------------------------
// K2: row softmax (in-place on g_sre/g_sim) + head-mean -> attn outputs.
// One block per (b,l): owns the (l)-row of all 8 heads for re and im.
// Each thread holds a float4 slice (s = 4*tid .. 4*tid+3) of the 1024-row.
// ---------------------------------------------------------------------------
__global__ void __launch_bounds__(256) k_softmax(float* __restrict__ out)
{
    __shared__ float red[8];
    const int bl = blockIdx.x;            // b*1024 + l
    const int tid = threadIdx.x;
    const int b = bl >> 10, l = bl & 1023;

    float4 mr = make_float4(0.f, 0.f, 0.f, 0.f);
    float4 mi = make_float4(0.f, 0.f, 0.f, 0.f);

    for (int h = 0; h < HH; h++) {
        size_t base = (((size_t)(b * HH + h)) * LL + l) * SS + ((size_t)tid << 2);
        float4 vr = *(float4*)(g_sre + base);
        float4 vi = *(float4*)(g_sim + base);

        // real part
        float mx = fmaxf(fmaxf(vr.x, vr.y), fmaxf(vr.z, vr.w));
        mx = block_max(mx, red);
        float4 er = make_float4(__expf(vr.x - mx), __expf(vr.y - mx),
                                __expf(vr.z - mx), __expf(vr.w - mx));
        float s = block_sum(er.x + er.y + er.z + er.w, red);
        float inv = 1.0f / s;
        er.x *= inv; er.y *= inv; er.z *= inv; er.w *= inv;
        *(float4*)(g_sre + base) = er;
        mr.x += er.x; mr.y += er.y; mr.z += er.z; mr.w += er.w;

        // imaginary part
        float mx2 = fmaxf(fmaxf(vi.x, vi.y), fmaxf(vi.z, vi.w));
        mx2 = block_max(mx2, red);
        float4 ei = make_float4(__expf(vi.x - mx2), __expf(vi.y - mx2),
                                __expf(vi.z - mx2), __expf(vi.w - mx2));
        float s2 = block_sum(ei.x + ei.y + ei.z + ei.w, red);
        float inv2 = 1.0f / s2;
        ei.x *= inv2; ei.y *= inv2; ei.z *= inv2; ei.w *= inv2;
        *(float4*)(g_sim + base) = ei;
        mi.x += ei.x; mi.y += ei.y; mi.z += ei.z; mi.w += ei.w;
    }

    const float wgt = 1.0f / (float)HH;
    mr.x *= wgt; mr.y *= wgt; mr.z *= wgt; mr.w *= wgt;
    mi.x *= wgt; mi.y *= wgt; mi.z *= wgt; mi.w *= wgt;
    size_t ao = (size_t)bl * SS + ((size_t)tid << 2);
    *(float4*)(out + ATTN_RE_OFF + ao) = mr;
    *(float4*)(out + ATTN_IM_OFF + ao) = mi;
}

// ---------------------------------------------------------------------------
// K3: output.  o_re = Ar Vr - Ai Vi,  o_im = Ar Vi + Ai Vr.
// Tile: 128 (l) x 64 (d = full Dh), looping s in chunks of 64.
// A tiles [row][s] pad-65 (broadcast scalar reads); V tiles [s][d] natural.
// ---------------------------------------------------------------------------
__global__ void __launch_bounds__(256, 2) k_out(
    const float* __restrict__ xre, const float* __restrict__ xim,
    float* __restrict__ out)
{
    extern __shared__ float sm[];
    float* asre = sm;                 // [128][65]
    float* asim = asre + 128 * 65;    // [128][65]
    float* vre  = asim + 128 * 65;    // [64][64]
    float* vim  = vre + 64 * 64;      // [64][64]

    const int bh = blockIdx.y;
    const int b = bh >> 3, h = bh & 7;
    const int l0 = blockIdx.x << 7;
    const int tid = threadIdx.x;
    const int tx = tid & 15, ty = tid >> 4;

    const float* xr = xre + (size_t)b * LL * DD + h * DHD;
    const float* xi = xim + (size_t)b * LL * DD + h * DHD;
    const float* ar_g = g_sre + ((size_t)bh * LL + l0) * SS;
    const float* ai_g = g_sim + ((size_t)bh * LL + l0) * SS;

    float ore[8][4], oim[8][4];
    #pragma unroll
    for (int r = 0; r < 8; r++)
        #pragma unroll
        for (int c = 0; c < 4; c++) { ore[r][c] = 0.f; oim[r][c] = 0.f; }

    for (int s0 = 0; s0 < SS; s0 += 64) {
        // A tiles: 128 rows x 64 s, coalesced, conflict-free STS
        #pragma unroll
        for (int i = 0; i < 32; i++) {
            int idx = tid + (i << 8);
            int row = idx >> 6, s = idx & 63;
            asre[row * 65 + s] = ar_g[(size_t)row * SS + s0 + s];
            asim[row * 65 + s] = ai_g[(size_t)row * SS + s0 + s];
        }
        // V tiles: 64 s x 64 d, natural layout
        #pragma unroll
        for (int i = 0; i < 16; i++) {
            int idx = tid + (i << 8);
            int s = idx >> 6, d = idx & 63;
            size_t g = (size_t)(s0 + s) * DD + d;
            vre[(s << 6) + d] = xr[g];
            vim[(s << 6) + d] = xi[g];
        }
        __syncthreads();

        const float* arb = asre + ty * 8 * 65;
        const float* aib = asim + ty * 8 * 65;
        for (int s = 0; s < 64; s++) {
            int vo = (s << 6) + (tx << 2);
            float4 v_r = *(const float4*)(vre + vo);
            float4 v_i = *(const float4*)(vim + vo);
            float vra[4] = { v_r.x, v_r.y, v_r.z, v_r.w };
            float via[4] = { v_i.x, v_i.y, v_i.z, v_i.w };
            #pragma unroll
            for (int r = 0; r < 8; r++) {
                float arv = arb[r * 65 + s];
                float aiv = aib[r * 65 + s];
                #pragma unroll
                for (int c = 0; c < 4; c++) {
                    ore[r][c] = fmaf(arv, vra[c], fmaf(-aiv, via[c], ore[r][c]));
                    oim[r][c] = fmaf(arv, via[c], fmaf( aiv, vra[c], oim[r][c]));
                }
            }
        }
        __syncthreads();
    }

    // out_re/out_im[b, l0+ty*8+r, h*64 + tx*4 .. +3]
    size_t ob = ((size_t)b * LL + l0 + ty * 8) * DD + h * DHD + (tx << 2);
    #pragma unroll
    for (int r = 0; r < 8; r++) {
        *(float4*)(out + OUT_RE_OFF + ob + (size_t)r * DD) =
            make_float4(ore[r][0], ore[r][1], ore[r][2], ore[r][3]);
        *(float4*)(out + OUT_IM_OFF + ob + (size_t)r * DD) =
            make_float4(oim[r][0], oim[r][1], oim[r][2], oim[r][3]);
    }
}

// ---------------------------------------------------------------------------
extern "C" void kernel_launch(void* const* d_in, const int* in_sizes, int n_in,
                              void* d_out, int out_size)
{
    const float* xre = (const float*)d_in[0];
    const float* xim = (const float*)d_in[1];
    float* outp = (float*)d_out;

    const int smem = (2 * 128 * 65 + 2 * 64 * 64) * 4;  // 99328 bytes
    cudaFuncSetAttribute(k_scores, cudaFuncAttributeMaxDynamicSharedMemorySize, smem);
    cudaFuncSetAttribute(k_out,    cudaFuncAttributeMaxDynamicSharedMemorySize, smem);

    k_scores<<<dim3(16, 8, 64), 256, smem>>>(xre, xim);
    k_softmax<<<BB * LL, 256>>>(outp);
    k_out<<<dim3(8, 64), 256, smem>>>(xre, xim, outp);
}

// round 4
// speedup vs baseline: 1.2166x; 1.2166x over previous
#include <cuda_runtime.h>
#include <math.h>
#include <stdint.h>

// Problem constants
#define BB 8
#define LL 1024
#define DD 512
#define HH 8
#define DHD 64
#define SS 1024
#define SCALE 0.125f

// Output section offsets (floats) in d_out: out_re | out_im | attn_re | attn_im
#define OUT_RE_OFF  0UL
#define OUT_IM_OFF  4194304UL
#define ATTN_RE_OFF 8388608UL
#define ATTN_IM_OFF 16777216UL

// Scratch: scaled scores, overwritten in-place by softmax probabilities.
__device__ float g_sre[(size_t)BB * HH * LL * SS];
__device__ float g_sim[(size_t)BB * HH * LL * SS];

// ---------------------------------------------------------------------------
// K1: scores. s_re = Qr Qr^T - Qi Qi^T, s_im = Qr Qi^T + Qi Qr^T (scaled).
// Both matrices are SYMMETRIC (q == k), so compute only tiles J >= I of a
// 16x16 grid of 64x64 tiles and mirror-write the off-diagonal tiles.
// 256 threads, 4x4 micro-tile, d unrolled by 4 with float4 Q fragments.
// ---------------------------------------------------------------------------
__global__ void __launch_bounds__(256, 2) k_scores(
    const float* __restrict__ xre, const float* __restrict__ xim)
{
    extern __shared__ float sm[];
    float* qre = sm;               // [64][68]
    float* qim = qre + 64 * 68;    // [64][68]
    float* kre = qim + 64 * 68;    // [64][64] swizzled [d][col]
    float* kim = kre + 64 * 64;    // [64][64] swizzled
    // total = 2*4352 + 2*4096 = 16896 floats = 67584 B

    const int bh = blockIdx.z;
    const int b = bh >> 3, h = bh & 7;

    // Unrank triangular tile index -> (I, J), J >= I, 16x16 tile grid
    int t = blockIdx.x, I = 0;
    while (t >= 16 - I) { t -= 16 - I; I++; }
    const int J = I + t;
    const int l0 = I << 6, s0 = J << 6;
    const int tid = threadIdx.x;

    const float* xr = xre + (size_t)b * LL * DD + h * DHD;
    const float* xi = xim + (size_t)b * LL * DD + h * DHD;

    // Load Q tile: 64 rows x 64 d, pad-68 (float4-aligned fragments)
    #pragma unroll
    for (int i = 0; i < 16; i++) {
        int idx = tid + (i << 8);
        int row = idx >> 6, d = idx & 63;
        size_t g = (size_t)(l0 + row) * DD + d;
        qre[row * 68 + d] = xr[g];
        qim[row * 68 + d] = xi[g];
    }
    // Load K tile transposed+swizzled: (col,d) -> d*64 + 4*((col>>2)^(d&15)) + (col&3)
    #pragma unroll
    for (int i = 0; i < 16; i++) {
        int idx = tid + (i << 8);
        int col = idx >> 6, d = idx & 63;
        int soff = (d << 6) + (((col >> 2) ^ (d & 15)) << 2) + (col & 3);
        size_t g = (size_t)(s0 + col) * DD + d;
        kre[soff] = xr[g];
        kim[soff] = xi[g];
    }
    __syncthreads();

    const int tx = tid & 15, ty = tid >> 4;     // 16 col-groups x 16 row-groups
    const float* qrb = qre + ty * 4 * 68;
    const float* qib = qim + ty * 4 * 68;

    float are[4][4], aim[4][4];
    #pragma unroll
    for (int r = 0; r < 4; r++)
        #pragma unroll
        for (int c = 0; c < 4; c++) { are[r][c] = 0.f; aim[r][c] = 0.f; }

    for (int d0 = 0; d0 < 64; d0 += 4) {
        float qr4[4][4], qi4[4][4];
        #pragma unroll
        for (int r = 0; r < 4; r++) {
            *(float4*)&qr4[r][0] = *(const float4*)(qrb + r * 68 + d0);
            *(float4*)&qi4[r][0] = *(const float4*)(qib + r * 68 + d0);
        }
        #pragma unroll
        for (int dd = 0; dd < 4; dd++) {
            int d = d0 + dd;
            int ko = (d << 6) + ((tx ^ (d & 15)) << 2);
            float4 krv = *(const float4*)(kre + ko);
            float4 kiv = *(const float4*)(kim + ko);
            float kra[4] = { krv.x, krv.y, krv.z, krv.w };
            float kia[4] = { kiv.x, kiv.y, kiv.z, kiv.w };
            #pragma unroll
            for (int r = 0; r < 4; r++) {
                float qr = qr4[r][dd], qi = qi4[r][dd];
                #pragma unroll
                for (int c = 0; c < 4; c++) {
                    are[r][c] = fmaf(qr, kra[c], fmaf(-qi, kia[c], are[r][c]));
                    aim[r][c] = fmaf(qr, kia[c], fmaf( qi, kra[c], aim[r][c]));
                }
            }
        }
    }

    // Scale
    #pragma unroll
    for (int r = 0; r < 4; r++)
        #pragma unroll
        for (int c = 0; c < 4; c++) { are[r][c] *= SCALE; aim[r][c] *= SCALE; }

    // Normal write: rows l0+ty*4+r, cols s0+tx*4..+3
    float* pre = g_sre + ((size_t)bh * LL + l0 + ty * 4) * SS + s0 + (tx << 2);
    float* pim = g_sim + ((size_t)bh * LL + l0 + ty * 4) * SS + s0 + (tx << 2);
    #pragma unroll
    for (int r = 0; r < 4; r++) {
        *(float4*)(pre + (size_t)r * SS) = make_float4(are[r][0], are[r][1], are[r][2], are[r][3]);
        *(float4*)(pim + (size_t)r * SS) = make_float4(aim[r][0], aim[r][1], aim[r][2], aim[r][3]);
    }

    // Mirror write for off-diagonal tiles: rows s0+tx*4+c, cols l0+ty*4..+3
    if (J > I) {
        float* mre = g_sre + ((size_t)bh * LL + s0 + (tx << 2)) * SS + l0 + ty * 4;
        float* mim = g_sim + ((size_t)bh * LL + s0 + (tx << 2)) * SS + l0 + ty * 4;
        #pragma unroll
        for (int c = 0; c < 4; c++) {
            *(float4*)(mre + (size_t)c * SS) = make_float4(are[0][c], are[1][c], are[2][c], are[3][c]);
            *(float4*)(mim + (size_t)c * SS) = make_float4(aim[0][c], aim[1][c], aim[2][c], aim[3][c]);
        }
    }
}

// ---------------------------------------------------------------------------
// K2: warp-per-head softmax (in-place) + head-mean -> attn outputs.
// Block = (b,l); warp w owns head w's full 1024 row (re and im).
// All reductions are warp-local shuffles; head-mean via 64KB smem staging.
// ---------------------------------------------------------------------------
__global__ void __launch_bounds__(256) k_softmax(float* __restrict__ out)
{
    extern __shared__ float psm[];      // pr[8][1024] | pi[8][1024]  (64 KB)
    float* pr = psm;
    float* pi = psm + 8 * 1024;

    const int bl = blockIdx.x;          // b*1024 + l
    const int tid = threadIdx.x;
    const int w = tid >> 5, ln = tid & 31;
    const int b = bl >> 10, l = bl & 1023;

    {
        const size_t base = (((size_t)(b * HH + w)) * LL + l) * SS;
        float4 vr[8], vi[8];
        #pragma unroll
        for (int j = 0; j < 8; j++) {
            size_t off = base + (size_t)(j * 128 + (ln << 2));
            vr[j] = *(const float4*)(g_sre + off);
            vi[j] = *(const float4*)(g_sim + off);
        }
        // max
        float mr = -3.4e38f, mi = -3.4e38f;
        #pragma unroll
        for (int j = 0; j < 8; j++) {
            mr = fmaxf(mr, fmaxf(fmaxf(vr[j].x, vr[j].y), fmaxf(vr[j].z, vr[j].w)));
            mi = fmaxf(mi, fmaxf(fmaxf(vi[j].x, vi[j].y), fmaxf(vi[j].z, vi[j].w)));
        }
        #pragma unroll
        for (int o = 16; o; o >>= 1) {
            mr = fmaxf(mr, __shfl_xor_sync(0xffffffffu, mr, o));
            mi = fmaxf(mi, __shfl_xor_sync(0xffffffffu, mi, o));
        }
        // exp + sum
        float sr = 0.f, si = 0.f;
        #pragma unroll
        for (int j = 0; j < 8; j++) {
            vr[j].x = __expf(vr[j].x - mr); vr[j].y = __expf(vr[j].y - mr);
            vr[j].z = __expf(vr[j].z - mr); vr[j].w = __expf(vr[j].w - mr);
            vi[j].x = __expf(vi[j].x - mi); vi[j].y = __expf(vi[j].y - mi);
            vi[j].z = __expf(vi[j].z - mi); vi[j].w = __expf(vi[j].w - mi);
            sr += vr[j].x + vr[j].y + vr[j].z + vr[j].w;
            si += vi[j].x + vi[j].y + vi[j].z + vi[j].w;
        }
        #pragma unroll
        for (int o = 16; o; o >>= 1) {
            sr += __shfl_xor_sync(0xffffffffu, sr, o);
            si += __shfl_xor_sync(0xffffffffu, si, o);
        }
        const float inr = 1.0f / sr, ini = 1.0f / si;
        #pragma unroll
        for (int j = 0; j < 8; j++) {
            vr[j].x *= inr; vr[j].y *= inr; vr[j].z *= inr; vr[j].w *= inr;
            vi[j].x *= ini; vi[j].y *= ini; vi[j].z *= ini; vi[j].w *= ini;
            size_t off = base + (size_t)(j * 128 + (ln << 2));
            *(float4*)(g_sre + off) = vr[j];
            *(float4*)(g_sim + off) = vi[j];
            int so = w * 1024 + j * 128 + (ln << 2);
            *(float4*)(pr + so) = vr[j];
            *(float4*)(pi + so) = vi[j];
        }
    }
    __syncthreads();

    // Head mean: thread tid owns s = 4*tid .. 4*tid+3
    float4 ar = make_float4(0.f, 0.f, 0.f, 0.f);
    float4 ai = make_float4(0.f, 0.f, 0.f, 0.f);
    #pragma unroll
    for (int h = 0; h < HH; h++) {
        float4 r = *(const float4*)(pr + h * 1024 + (tid << 2));
        float4 m = *(const float4*)(pi + h * 1024 + (tid << 2));
        ar.x += r.x; ar.y += r.y; ar.z += r.z; ar.w += r.w;
        ai.x += m.x; ai.y += m.y; ai.z += m.z; ai.w += m.w;
    }
    const float wgt = 1.0f / (float)HH;
    ar.x *= wgt; ar.y *= wgt; ar.z *= wgt; ar.w *= wgt;
    ai.x *= wgt; ai.y *= wgt; ai.z *= wgt; ai.w *= wgt;
    size_t ao = (size_t)bl * SS + ((size_t)tid << 2);
    *(float4*)(out + ATTN_RE_OFF + ao) = ar;
    *(float4*)(out + ATTN_IM_OFF + ao) = ai;
}

// ---------------------------------------------------------------------------
// K3: output. o_re = Ar Vr - Ai Vi, o_im = Ar Vi + Ai Vr.
// Tile: 128 (l) x 64 (d = full Dh), looping s in chunks of 64.
// 256 threads, 4x8 micro-tile, s unrolled by 4 with float4 A fragments.
// ---------------------------------------------------------------------------
__global__ void __launch_bounds__(256, 2) k_out(
    const float* __restrict__ xre, const float* __restrict__ xim,
    float* __restrict__ out)
{
    extern __shared__ float sm[];
    float* asre = sm;                 // [128][68]
    float* asim = asre + 128 * 68;    // [128][68]
    float* vre  = asim + 128 * 68;    // [64][64]
    float* vim  = vre + 64 * 64;      // [64][64]
    // total = 2*8704 + 2*4096 = 25600 floats = 102400 B

    const int bh = blockIdx.y;
    const int b = bh >> 3, h = bh & 7;
    const int l0 = blockIdx.x << 7;
    const int tid = threadIdx.x;
    const int tx = tid & 7, ty = tid >> 3;   // 8 col-groups x 32 row-groups

    const float* xr = xre + (size_t)b * LL * DD + h * DHD;
    const float* xi = xim + (size_t)b * LL * DD + h * DHD;
    const float* ar_g = g_sre + ((size_t)bh * LL + l0) * SS;
    const float* ai_g = g_sim + ((size_t)bh * LL + l0) * SS;

    float ore[4][8], oim[4][8];
    #pragma unroll
    for (int r = 0; r < 4; r++)
        #pragma unroll
        for (int c = 0; c < 8; c++) { ore[r][c] = 0.f; oim[r][c] = 0.f; }

    for (int s0 = 0; s0 < SS; s0 += 64) {
        // A tiles: 128 rows x 64 s, pad-68
        #pragma unroll
        for (int i = 0; i < 32; i++) {
            int idx = tid + (i << 8);
            int row = idx >> 6, s = idx & 63;
            asre[row * 68 + s] = ar_g[(size_t)row * SS + s0 + s];
            asim[row * 68 + s] = ai_g[(size_t)row * SS + s0 + s];
        }
        // V tiles: 64 s x 64 d, natural layout
        #pragma unroll
        for (int i = 0; i < 16; i++) {
            int idx = tid + (i << 8);
            int s = idx >> 6, d = idx & 63;
            size_t g = (size_t)(s0 + s) * DD + d;
            vre[(s << 6) + d] = xr[g];
            vim[(s << 6) + d] = xi[g];
        }
        __syncthreads();

        const float* arb = asre + ty * 4 * 68;
        const float* aib = asim + ty * 4 * 68;
        for (int ss = 0; ss < 64; ss += 4) {
            float ar4[4][4], ai4[4][4];
            #pragma unroll
            for (int r = 0; r < 4; r++) {
                *(float4*)&ar4[r][0] = *(const float4*)(arb + r * 68 + ss);
                *(float4*)&ai4[r][0] = *(const float4*)(aib + r * 68 + ss);
            }
            #pragma unroll
            for (int dd = 0; dd < 4; dd++) {
                int s = ss + dd;
                int vo = (s << 6) + (tx << 3);
                float4 vr0 = *(const float4*)(vre + vo);
                float4 vr1 = *(const float4*)(vre + vo + 4);
                float4 vi0 = *(const float4*)(vim + vo);
                float4 vi1 = *(const float4*)(vim + vo + 4);
                float vra[8] = { vr0.x, vr0.y, vr0.z, vr0.w, vr1.x, vr1.y, vr1.z, vr1.w };
                float via[8] = { vi0.x, vi0.y, vi0.z, vi0.w, vi1.x, vi1.y, vi1.z, vi1.w };
                #pragma unroll
                for (int r = 0; r < 4; r++) {
                    float arv = ar4[r][dd], aiv = ai4[r][dd];
                    #pragma unroll
                    for (int c = 0; c < 8; c++) {
                        ore[r][c] = fmaf(arv, vra[c], fmaf(-aiv, via[c], ore[r][c]));
                        oim[r][c] = fmaf(arv, via[c], fmaf( aiv, vra[c], oim[r][c]));
                    }
                }
            }
        }
        __syncthreads();
    }

    // out[b, l0+ty*4+r, h*64 + tx*8 .. +7]
    size_t ob = ((size_t)b * LL + l0 + ty * 4) * DD + h * DHD + (tx << 3);
    #pragma unroll
    for (int r = 0; r < 4; r++) {
        *(float4*)(out + OUT_RE_OFF + ob + (size_t)r * DD) =
            make_float4(ore[r][0], ore[r][1], ore[r][2], ore[r][3]);
        *(float4*)(out + OUT_RE_OFF + ob + (size_t)r * DD + 4) =
            make_float4(ore[r][4], ore[r][5], ore[r][6], ore[r][7]);
        *(float4*)(out + OUT_IM_OFF + ob + (size_t)r * DD) =
            make_float4(oim[r][0], oim[r][1], oim[r][2], oim[r][3]);
        *(float4*)(out + OUT_IM_OFF + ob + (size_t)r * DD + 4) =
            make_float4(oim[r][4], oim[r][5], oim[r][6], oim[r][7]);
    }
}

// ---------------------------------------------------------------------------
extern "C" void kernel_launch(void* const* d_in, const int* in_sizes, int n_in,
                              void* d_out, int out_size)
{
    const float* xre = (const float*)d_in[0];
    const float* xim = (const float*)d_in[1];
    float* outp = (float*)d_out;

    const int smem1 = (2 * 64 * 68 + 2 * 64 * 64) * 4;    // 67584 B
    const int smem2 = 2 * 8 * 1024 * 4;                    // 65536 B
    const int smem3 = (2 * 128 * 68 + 2 * 64 * 64) * 4;   // 102400 B
    cudaFuncSetAttribute(k_scores,  cudaFuncAttributeMaxDynamicSharedMemorySize, smem1);
    cudaFuncSetAttribute(k_softmax, cudaFuncAttributeMaxDynamicSharedMemorySize, smem2);
    cudaFuncSetAttribute(k_out,     cudaFuncAttributeMaxDynamicSharedMemorySize, smem3);

    k_scores<<<dim3(136, 1, 64), 256, smem1>>>(xre, xim);
    k_softmax<<<BB * LL, 256, smem2>>>(outp);
    k_out<<<dim3(8, 64), 256, smem3>>>(xre, xim, outp);
}

// round 8
// speedup vs baseline: 2.2120x; 1.8182x over previous
#include <cuda_runtime.h>
#include <cuda_bf16.h>
#include <math.h>
#include <stdint.h>

// Problem constants
#define BB 8
#define LL 1024
#define DD 512
#define HH 8
#define SS 1024
#define SCALE 0.125f

// Output sections (floats): out_re | out_im | attn_re | attn_im
#define OUT_RE_OFF  0UL
#define OUT_IM_OFF  4194304UL
#define ATTN_RE_OFF 8388608UL
#define ATTN_IM_OFF 16777216UL

// Scratch
__device__ float g_sre[(size_t)BB * HH * LL * SS];           // scaled scores re
__device__ float g_sim[(size_t)BB * HH * LL * SS];           // scaled scores im
__device__ __nv_bfloat16 g_p0r[(size_t)BB * HH * LL * SS];   // prob splits
__device__ __nv_bfloat16 g_p1r[(size_t)BB * HH * LL * SS];
__device__ __nv_bfloat16 g_p0i[(size_t)BB * HH * LL * SS];
__device__ __nv_bfloat16 g_p1i[(size_t)BB * HH * LL * SS];

// ---------------------------------------------------------------------------
// Helpers (plain sm_80+ PTX only — no 'a'-gated features)
// ---------------------------------------------------------------------------
__device__ __forceinline__ uint32_t smem_u32(const void* p) {
    uint32_t a;
    asm("{ .reg .u64 t; cvta.to.shared.u64 t, %1; cvt.u32.u64 %0, t; }"
        : "=r"(a) : "l"(p));
    return a;
}

__device__ __forceinline__ uint32_t pack_bf(__nv_bfloat16 a, __nv_bfloat16 b) {
    __nv_bfloat162 t(a, b);
    return *reinterpret_cast<uint32_t*>(&t);
}

__device__ __forceinline__ void split_pack(float f0, float f1, uint32_t& hi, uint32_t& lo) {
    __nv_bfloat16 h0 = __float2bfloat16(f0), h1 = __float2bfloat16(f1);
    float r0 = f0 - __bfloat162float(h0), r1 = f1 - __bfloat162float(h1);
    hi = pack_bf(h0, h1);
    lo = pack_bf(__float2bfloat16(r0), __float2bfloat16(r1));
}

__device__ __forceinline__ void ldsm4(uint32_t& r0, uint32_t& r1, uint32_t& r2,
                                      uint32_t& r3, uint32_t addr) {
    asm volatile("ldmatrix.sync.aligned.m8n8.x4.shared.b16 {%0,%1,%2,%3}, [%4];"
                 : "=r"(r0), "=r"(r1), "=r"(r2), "=r"(r3) : "r"(addr));
}

__device__ __forceinline__ void ldsm4t(uint32_t& r0, uint32_t& r1, uint32_t& r2,
                                       uint32_t& r3, uint32_t addr) {
    asm volatile("ldmatrix.sync.aligned.m8n8.x4.trans.shared.b16 {%0,%1,%2,%3}, [%4];"
                 : "=r"(r0), "=r"(r1), "=r"(r2), "=r"(r3) : "r"(addr));
}

__device__ __forceinline__ void mma_bf16(float c[4], const uint32_t a[4],
                                         const uint32_t b[2]) {
    asm volatile("mma.sync.aligned.m16n8k16.row.col.f32.bf16.bf16.f32 "
                 "{%0,%1,%2,%3}, {%4,%5,%6,%7}, {%8,%9}, {%0,%1,%2,%3};"
                 : "+f"(c[0]), "+f"(c[1]), "+f"(c[2]), "+f"(c[3])
                 : "r"(a[0]), "r"(a[1]), "r"(a[2]), "r"(a[3]),
                   "r"(b[0]), "r"(b[1]));
}

#define PAD  72
#define ROWB 144   // bytes per padded row (72 bf16) — ldmatrix conflict-free

// ---------------------------------------------------------------------------
// K1: scores via mma.sync bf16 split.  CTA tile 128(l) x 64(s), K = Dh = 64.
// SMEM: A arrays (Qr_hi,Qr_lo,Qi_hi,Qi_lo) 128x72 bf16 @ arr*18432;
//       B arrays (Kr_hi,Kr_lo,Ki_hi,Ki_lo)  64x72 bf16 @ 73728 + arr*9216.
// 8 warps, warp tile 32x32 (2 m-tiles x 4 n-tiles of m16n8).
// re = Qr·Kr − Qi·Ki (minus via negated Qi frags), im = Qr·Ki + Qi·Kr.
// ---------------------------------------------------------------------------
#define K1_SMEM 110592

__global__ void __launch_bounds__(256) k1_scores(
    const float* __restrict__ xre, const float* __restrict__ xim)
{
    extern __shared__ char sm_[];
    const uint32_t sb = smem_u32(sm_);
    const int tid = threadIdx.x, wid = tid >> 5, lane = tid & 31;
    const int bh = blockIdx.z, b = bh >> 3, h = bh & 7;
    const int l0 = blockIdx.y << 7, s0 = blockIdx.x << 6;

    const float* xr = xre + (size_t)b * LL * DD + h * 64;
    const float* xi = xim + (size_t)b * LL * DD + h * 64;

    // Fill A side: 128 rows x 32 col-pairs
    #pragma unroll
    for (int i = 0; i < 16; i++) {
        int idx = tid + (i << 8);
        int row = idx >> 5, cp = idx & 31;
        uint32_t off = (uint32_t)(row * ROWB + cp * 4);
        size_t g = (size_t)(l0 + row) * DD + cp * 2;
        float2 fr = *(const float2*)(xr + g);
        float2 fi = *(const float2*)(xi + g);
        uint32_t hw0, lw0, hw1, lw1;
        split_pack(fr.x, fr.y, hw0, lw0);
        split_pack(fi.x, fi.y, hw1, lw1);
        *(uint32_t*)(sm_ + 0 * 18432 + off) = hw0;
        *(uint32_t*)(sm_ + 1 * 18432 + off) = lw0;
        *(uint32_t*)(sm_ + 2 * 18432 + off) = hw1;
        *(uint32_t*)(sm_ + 3 * 18432 + off) = lw1;
    }
    // Fill B side: 64 rows x 32 col-pairs
    #pragma unroll
    for (int i = 0; i < 8; i++) {
        int idx = tid + (i << 8);
        int row = idx >> 5, cp = idx & 31;
        uint32_t off = 73728u + (uint32_t)(row * ROWB + cp * 4);
        size_t g = (size_t)(s0 + row) * DD + cp * 2;
        float2 fr = *(const float2*)(xr + g);
        float2 fi = *(const float2*)(xi + g);
        uint32_t hw0, lw0, hw1, lw1;
        split_pack(fr.x, fr.y, hw0, lw0);
        split_pack(fi.x, fi.y, hw1, lw1);
        *(uint32_t*)(sm_ + 0 * 9216 + off) = hw0;
        *(uint32_t*)(sm_ + 1 * 9216 + off) = lw0;
        *(uint32_t*)(sm_ + 2 * 9216 + off) = hw1;
        *(uint32_t*)(sm_ + 3 * 9216 + off) = lw1;
    }
    __syncthreads();

    const int m0 = (wid >> 1) * 32, n0 = (wid & 1) * 32;
    float cre[2][4][4], cim[2][4][4];
    #pragma unroll
    for (int mt = 0; mt < 2; mt++)
        #pragma unroll
        for (int nt = 0; nt < 4; nt++)
            #pragma unroll
            for (int j = 0; j < 4; j++) { cre[mt][nt][j] = 0.f; cim[mt][nt][j] = 0.f; }

    #pragma unroll
    for (int k0 = 0; k0 < 64; k0 += 16) {
        // A fragments: [arr][mt][4]
        uint32_t a[4][2][4];
        #pragma unroll
        for (int arr = 0; arr < 4; arr++)
            #pragma unroll
            for (int mt = 0; mt < 2; mt++) {
                uint32_t ad = sb + arr * 18432 +
                    (uint32_t)((m0 + mt * 16 + (lane & 15)) * ROWB +
                               (k0 + ((lane >> 4) << 3)) * 2);
                ldsm4(a[arr][mt][0], a[arr][mt][1], a[arr][mt][2], a[arr][mt][3], ad);
            }
        // B fragments: [arr][nt][2]
        uint32_t bf[4][4][2];
        #pragma unroll
        for (int arr = 0; arr < 4; arr++)
            #pragma unroll
            for (int p = 0; p < 2; p++) {
                uint32_t r0, r1, r2, r3;
                uint32_t ad = sb + 73728u + arr * 9216 +
                    (uint32_t)((n0 + p * 16 + ((lane >> 4) << 3) + (lane & 7)) * ROWB +
                               (k0 + (((lane >> 3) & 1) << 3)) * 2);
                ldsm4(r0, r1, r2, r3, ad);
                bf[arr][2 * p][0] = r0;     bf[arr][2 * p][1] = r1;
                bf[arr][2 * p + 1][0] = r2; bf[arr][2 * p + 1][1] = r3;
            }
        // Negated Qi fragments (hi, lo)
        uint32_t na[2][2][4];
        #pragma unroll
        for (int s = 0; s < 2; s++)
            #pragma unroll
            for (int mt = 0; mt < 2; mt++)
                #pragma unroll
                for (int j = 0; j < 4; j++)
                    na[s][mt][j] = a[2 + s][mt][j] ^ 0x80008000u;

        #pragma unroll
        for (int mt = 0; mt < 2; mt++)
            #pragma unroll
            for (int nt = 0; nt < 4; nt++) {
                mma_bf16(cre[mt][nt], a[0][mt],  bf[0][nt]);   // Qr_h·Kr_h
                mma_bf16(cre[mt][nt], a[0][mt],  bf[1][nt]);   // Qr_h·Kr_l
                mma_bf16(cre[mt][nt], a[1][mt],  bf[0][nt]);   // Qr_l·Kr_h
                mma_bf16(cre[mt][nt], na[0][mt], bf[2][nt]);   // -Qi_h·Ki_h
                mma_bf16(cre[mt][nt], na[0][mt], bf[3][nt]);   // -Qi_h·Ki_l
                mma_bf16(cre[mt][nt], na[1][mt], bf[2][nt]);   // -Qi_l·Ki_h
                mma_bf16(cim[mt][nt], a[0][mt],  bf[2][nt]);   // Qr_h·Ki_h
                mma_bf16(cim[mt][nt], a[0][mt],  bf[3][nt]);
                mma_bf16(cim[mt][nt], a[1][mt],  bf[2][nt]);
                mma_bf16(cim[mt][nt], a[2][mt],  bf[0][nt]);   // Qi_h·Kr_h
                mma_bf16(cim[mt][nt], a[2][mt],  bf[1][nt]);
                mma_bf16(cim[mt][nt], a[3][mt],  bf[0][nt]);
            }
    }

    // Epilogue: scale + direct float2 stores
    #pragma unroll
    for (int mt = 0; mt < 2; mt++)
        #pragma unroll
        for (int nt = 0; nt < 4; nt++) {
            int row = l0 + m0 + mt * 16 + (lane >> 2);
            int col = s0 + n0 + nt * 8 + ((lane & 3) << 1);
            size_t base = ((size_t)bh * LL + row) * SS + col;
            *(float2*)(g_sre + base) =
                make_float2(cre[mt][nt][0] * SCALE, cre[mt][nt][1] * SCALE);
            *(float2*)(g_sre + base + 8 * SS) =
                make_float2(cre[mt][nt][2] * SCALE, cre[mt][nt][3] * SCALE);
            *(float2*)(g_sim + base) =
                make_float2(cim[mt][nt][0] * SCALE, cim[mt][nt][1] * SCALE);
            *(float2*)(g_sim + base + 8 * SS) =
                make_float2(cim[mt][nt][2] * SCALE, cim[mt][nt][3] * SCALE);
        }
}

// ---------------------------------------------------------------------------
// K2: warp-per-head softmax + head-mean.  Emits bf16 split prob pairs.
// ---------------------------------------------------------------------------
__global__ void __launch_bounds__(256) k_softmax(float* __restrict__ out)
{
    extern __shared__ float psm[];      // pr[8][1024] | pi[8][1024]
    float* pr = psm;
    float* pi = psm + 8 * 1024;

    const int bl = blockIdx.x;
    const int tid = threadIdx.x;
    const int w = tid >> 5, ln = tid & 31;
    const int b = bl >> 10, l = bl & 1023;

    {
        const size_t base = (((size_t)(b * HH + w)) * LL + l) * SS;
        float4 vr[8], vi[8];
        #pragma unroll
        for (int j = 0; j < 8; j++) {
            size_t off = base + (size_t)(j * 128 + (ln << 2));
            vr[j] = *(const float4*)(g_sre + off);
            vi[j] = *(const float4*)(g_sim + off);
        }
        float mr = -3.4e38f, mi = -3.4e38f;
        #pragma unroll
        for (int j = 0; j < 8; j++) {
            mr = fmaxf(mr, fmaxf(fmaxf(vr[j].x, vr[j].y), fmaxf(vr[j].z, vr[j].w)));
            mi = fmaxf(mi, fmaxf(fmaxf(vi[j].x, vi[j].y), fmaxf(vi[j].z, vi[j].w)));
        }
        #pragma unroll
        for (int o = 16; o; o >>= 1) {
            mr = fmaxf(mr, __shfl_xor_sync(0xffffffffu, mr, o));
            mi = fmaxf(mi, __shfl_xor_sync(0xffffffffu, mi, o));
        }
        float sr = 0.f, si = 0.f;
        #pragma unroll
        for (int j = 0; j < 8; j++) {
            vr[j].x = __expf(vr[j].x - mr); vr[j].y = __expf(vr[j].y - mr);
            vr[j].z = __expf(vr[j].z - mr); vr[j].w = __expf(vr[j].w - mr);
            vi[j].x = __expf(vi[j].x - mi); vi[j].y = __expf(vi[j].y - mi);
            vi[j].z = __expf(vi[j].z - mi); vi[j].w = __expf(vi[j].w - mi);
            sr += vr[j].x + vr[j].y + vr[j].z + vr[j].w;
            si += vi[j].x + vi[j].y + vi[j].z + vi[j].w;
        }
        #pragma unroll
        for (int o = 16; o; o >>= 1) {
            sr += __shfl_xor_sync(0xffffffffu, sr, o);
            si += __shfl_xor_sync(0xffffffffu, si, o);
        }
        const float inr = 1.0f / sr, ini = 1.0f / si;
        #pragma unroll
        for (int j = 0; j < 8; j++) {
            vr[j].x *= inr; vr[j].y *= inr; vr[j].z *= inr; vr[j].w *= inr;
            vi[j].x *= ini; vi[j].y *= ini; vi[j].z *= ini; vi[j].w *= ini;
            size_t off = base + (size_t)(j * 128 + (ln << 2));
            uint32_t h01, l01, h23, l23;
            split_pack(vr[j].x, vr[j].y, h01, l01);
            split_pack(vr[j].z, vr[j].w, h23, l23);
            *(uint32_t*)(g_p0r + off)     = h01;
            *(uint32_t*)(g_p0r + off + 2) = h23;
            *(uint32_t*)(g_p1r + off)     = l01;
            *(uint32_t*)(g_p1r + off + 2) = l23;
            split_pack(vi[j].x, vi[j].y, h01, l01);
            split_pack(vi[j].z, vi[j].w, h23, l23);
            *(uint32_t*)(g_p0i + off)     = h01;
            *(uint32_t*)(g_p0i + off + 2) = h23;
            *(uint32_t*)(g_p1i + off)     = l01;
            *(uint32_t*)(g_p1i + off + 2) = l23;
            int so = w * 1024 + j * 128 + (ln << 2);
            *(float4*)(pr + so) = vr[j];
            *(float4*)(pi + so) = vi[j];
        }
    }
    __syncthreads();

    float4 ar = make_float4(0.f, 0.f, 0.f, 0.f);
    float4 ai = make_float4(0.f, 0.f, 0.f, 0.f);
    #pragma unroll
    for (int hh = 0; hh < HH; hh++) {
        float4 r = *(const float4*)(pr + hh * 1024 + (tid << 2));
        float4 m = *(const float4*)(pi + hh * 1024 + (tid << 2));
        ar.x += r.x; ar.y += r.y; ar.z += r.z; ar.w += r.w;
        ai.x += m.x; ai.y += m.y; ai.z += m.z; ai.w += m.w;
    }
    const float wgt = 1.0f / (float)HH;
    ar.x *= wgt; ar.y *= wgt; ar.z *= wgt; ar.w *= wgt;
    ai.x *= wgt; ai.y *= wgt; ai.z *= wgt; ai.w *= wgt;
    size_t ao = (size_t)bl * SS + ((size_t)tid << 2);
    *(float4*)(out + ATTN_RE_OFF + ao) = ar;
    *(float4*)(out + ATTN_IM_OFF + ao) = ai;
}

// ---------------------------------------------------------------------------
// K3: output via mma.sync bf16 split.  CTA tile 128(l) x 64(d), K = S = 1024
// in 16 chunks of 64.  A = prob splits [l][s] (straight copies);
// B = V stored [s][d] in smem, fragments via ldmatrix.x4.trans.
// O_re = Ar·Vr − Ai·Vi (minus via negated Ai frags), O_im = Ar·Vi + Ai·Vr.
// SMEM: A arrays 128x72 @ arr*18432; V arrays 64x72 @ 73728 + arr*9216.
// ---------------------------------------------------------------------------
#define K3_SMEM 110592

__global__ void __launch_bounds__(256) k3_out(
    const float* __restrict__ xre, const float* __restrict__ xim,
    float* __restrict__ out)
{
    extern __shared__ char sm_[];
    const uint32_t sb = smem_u32(sm_);
    const int tid = threadIdx.x, wid = tid >> 5, lane = tid & 31;
    const int bh = blockIdx.y, b = bh >> 3, h = bh & 7;
    const int l0 = blockIdx.x << 7;

    const float* xr = xre + (size_t)b * LL * DD + h * 64;
    const float* xi = xim + (size_t)b * LL * DD + h * 64;
    const __nv_bfloat16* gpa[4] = { g_p0r, g_p1r, g_p0i, g_p1i };
    const size_t abase = (size_t)bh * LL + l0;

    const int m0 = (wid >> 1) * 32, n0 = (wid & 1) * 32;
    float cre[2][4][4], cim[2][4][4];
    #pragma unroll
    for (int mt = 0; mt < 2; mt++)
        #pragma unroll
        for (int nt = 0; nt < 4; nt++)
            #pragma unroll
            for (int j = 0; j < 4; j++) { cre[mt][nt][j] = 0.f; cim[mt][nt][j] = 0.f; }

    for (int c = 0; c < 16; c++) {
        // Fill A: 4 arrays x 128 rows x 32 col-pair words (straight copies)
        #pragma unroll
        for (int arr = 0; arr < 4; arr++) {
            const __nv_bfloat16* gp = gpa[arr];
            #pragma unroll
            for (int i = 0; i < 16; i++) {
                int idx = tid + (i << 8);
                int row = idx >> 5, cp = idx & 31;
                uint32_t wv = *(const uint32_t*)(gp + (abase + row) * SS + c * 64 + cp * 2);
                *(uint32_t*)(sm_ + arr * 18432 + row * ROWB + cp * 4) = wv;
            }
        }
        // Fill V: 64 s-rows x 32 d-pairs, split on the fly, layout [s][d]
        #pragma unroll
        for (int i = 0; i < 8; i++) {
            int idx = tid + (i << 8);
            int row = idx >> 5, cp = idx & 31;
            uint32_t off = 73728u + (uint32_t)(row * ROWB + cp * 4);
            size_t g = (size_t)(c * 64 + row) * DD + cp * 2;
            float2 fr = *(const float2*)(xr + g);
            float2 fi = *(const float2*)(xi + g);
            uint32_t hw0, lw0, hw1, lw1;
            split_pack(fr.x, fr.y, hw0, lw0);
            split_pack(fi.x, fi.y, hw1, lw1);
            *(uint32_t*)(sm_ + 0 * 9216 + off) = hw0;
            *(uint32_t*)(sm_ + 1 * 9216 + off) = lw0;
            *(uint32_t*)(sm_ + 2 * 9216 + off) = hw1;
            *(uint32_t*)(sm_ + 3 * 9216 + off) = lw1;
        }
        __syncthreads();

        #pragma unroll
        for (int k0 = 0; k0 < 64; k0 += 16) {
            uint32_t a[4][2][4];
            #pragma unroll
            for (int arr = 0; arr < 4; arr++)
                #pragma unroll
                for (int mt = 0; mt < 2; mt++) {
                    uint32_t ad = sb + arr * 18432 +
                        (uint32_t)((m0 + mt * 16 + (lane & 15)) * ROWB +
                                   (k0 + ((lane >> 4) << 3)) * 2);
                    ldsm4(a[arr][mt][0], a[arr][mt][1], a[arr][mt][2], a[arr][mt][3], ad);
                }
            uint32_t bf[4][4][2];
            #pragma unroll
            for (int arr = 0; arr < 4; arr++)
                #pragma unroll
                for (int p = 0; p < 2; p++) {
                    uint32_t r0, r1, r2, r3;
                    uint32_t ad = sb + 73728u + arr * 9216 +
                        (uint32_t)((k0 + (((lane >> 3) & 1) << 3) + (lane & 7)) * ROWB +
                                   (n0 + p * 16 + ((lane >> 4) << 3)) * 2);
                    ldsm4t(r0, r1, r2, r3, ad);
                    bf[arr][2 * p][0] = r0;     bf[arr][2 * p][1] = r1;
                    bf[arr][2 * p + 1][0] = r2; bf[arr][2 * p + 1][1] = r3;
                }
            uint32_t na[2][2][4];
            #pragma unroll
            for (int s = 0; s < 2; s++)
                #pragma unroll
                for (int mt = 0; mt < 2; mt++)
                    #pragma unroll
                    for (int j = 0; j < 4; j++)
                        na[s][mt][j] = a[2 + s][mt][j] ^ 0x80008000u;

            #pragma unroll
            for (int mt = 0; mt < 2; mt++)
                #pragma unroll
                for (int nt = 0; nt < 4; nt++) {
                    mma_bf16(cre[mt][nt], a[0][mt],  bf[0][nt]);   // Ar_h·Vr_h
                    mma_bf16(cre[mt][nt], a[0][mt],  bf[1][nt]);   // Ar_h·Vr_l
                    mma_bf16(cre[mt][nt], a[1][mt],  bf[0][nt]);   // Ar_l·Vr_h
                    mma_bf16(cre[mt][nt], na[0][mt], bf[2][nt]);   // -Ai_h·Vi_h
                    mma_bf16(cre[mt][nt], na[0][mt], bf[3][nt]);   // -Ai_h·Vi_l
                    mma_bf16(cre[mt][nt], na[1][mt], bf[2][nt]);   // -Ai_l·Vi_h
                    mma_bf16(cim[mt][nt], a[0][mt],  bf[2][nt]);   // Ar_h·Vi_h
                    mma_bf16(cim[mt][nt], a[0][mt],  bf[3][nt]);
                    mma_bf16(cim[mt][nt], a[1][mt],  bf[2][nt]);
                    mma_bf16(cim[mt][nt], a[2][mt],  bf[0][nt]);   // Ai_h·Vr_h
                    mma_bf16(cim[mt][nt], a[2][mt],  bf[1][nt]);
                    mma_bf16(cim[mt][nt], a[3][mt],  bf[0][nt]);
                }
        }
        __syncthreads();
    }

    // Epilogue: direct float2 stores to out
    #pragma unroll
    for (int mt = 0; mt < 2; mt++)
        #pragma unroll
        for (int nt = 0; nt < 4; nt++) {
            int row = l0 + m0 + mt * 16 + (lane >> 2);
            int col = h * 64 + n0 + nt * 8 + ((lane & 3) << 1);
            size_t base = ((size_t)b * LL + row) * DD + col;
            *(float2*)(out + OUT_RE_OFF + base) =
                make_float2(cre[mt][nt][0], cre[mt][nt][1]);
            *(float2*)(out + OUT_RE_OFF + base + 8 * DD) =
                make_float2(cre[mt][nt][2], cre[mt][nt][3]);
            *(float2*)(out + OUT_IM_OFF + base) =
                make_float2(cim[mt][nt][0], cim[mt][nt][1]);
            *(float2*)(out + OUT_IM_OFF + base + 8 * DD) =
                make_float2(cim[mt][nt][2], cim[mt][nt][3]);
        }
}

// ---------------------------------------------------------------------------
extern "C" void kernel_launch(void* const* d_in, const int* in_sizes, int n_in,
                              void* d_out, int out_size)
{
    const float* xre = (const float*)d_in[0];
    const float* xim = (const float*)d_in[1];
    float* outp = (float*)d_out;

    const int smem2 = 2 * 8 * 1024 * 4;  // 65536
    cudaFuncSetAttribute(k1_scores, cudaFuncAttributeMaxDynamicSharedMemorySize, K1_SMEM);
    cudaFuncSetAttribute(k_softmax, cudaFuncAttributeMaxDynamicSharedMemorySize, smem2);
    cudaFuncSetAttribute(k3_out,    cudaFuncAttributeMaxDynamicSharedMemorySize, K3_SMEM);

    k1_scores<<<dim3(16, 8, 64), 256, K1_SMEM>>>(xre, xim);
    k_softmax<<<BB * LL, 256, smem2>>>(outp);
    k3_out<<<dim3(8, 64), 256, K3_SMEM>>>(xre, xim, outp);
}

// round 9
// speedup vs baseline: 2.4716x; 1.1174x over previous
#include <cuda_runtime.h>
#include <cuda_bf16.h>
#include <math.h>
#include <stdint.h>

// Problem constants
#define BB 8
#define LL 1024
#define DD 512
#define HH 8
#define SS 1024
#define SCALE 0.125f

// Output sections (floats): out_re | out_im | attn_re | attn_im
#define OUT_RE_OFF  0UL
#define OUT_IM_OFF  4194304UL
#define ATTN_RE_OFF 8388608UL
#define ATTN_IM_OFF 16777216UL

// Scratch
__device__ float g_sre[(size_t)BB * HH * LL * SS];           // scaled scores re
__device__ float g_sim[(size_t)BB * HH * LL * SS];           // scaled scores im
__device__ __nv_bfloat16 g_p0r[(size_t)BB * HH * LL * SS];   // prob splits
__device__ __nv_bfloat16 g_p1r[(size_t)BB * HH * LL * SS];
__device__ __nv_bfloat16 g_p0i[(size_t)BB * HH * LL * SS];
__device__ __nv_bfloat16 g_p1i[(size_t)BB * HH * LL * SS];

// ---------------------------------------------------------------------------
// Helpers (plain sm_80+ PTX only)
// ---------------------------------------------------------------------------
__device__ __forceinline__ uint32_t smem_u32(const void* p) {
    uint32_t a;
    asm("{ .reg .u64 t; cvta.to.shared.u64 t, %1; cvt.u32.u64 %0, t; }"
        : "=r"(a) : "l"(p));
    return a;
}

__device__ __forceinline__ uint32_t pack_bf(__nv_bfloat16 a, __nv_bfloat16 b) {
    __nv_bfloat162 t(a, b);
    return *reinterpret_cast<uint32_t*>(&t);
}

__device__ __forceinline__ void split_pack(float f0, float f1, uint32_t& hi, uint32_t& lo) {
    __nv_bfloat16 h0 = __float2bfloat16(f0), h1 = __float2bfloat16(f1);
    float r0 = f0 - __bfloat162float(h0), r1 = f1 - __bfloat162float(h1);
    hi = pack_bf(h0, h1);
    lo = pack_bf(__float2bfloat16(r0), __float2bfloat16(r1));
}

__device__ __forceinline__ float2 bf2_to_f2(uint32_t w) {
    __nv_bfloat162 t = *reinterpret_cast<__nv_bfloat162*>(&w);
    return make_float2(__low2float(t), __high2float(t));
}

__device__ __forceinline__ void ldsm4(uint32_t& r0, uint32_t& r1, uint32_t& r2,
                                      uint32_t& r3, uint32_t addr) {
    asm volatile("ldmatrix.sync.aligned.m8n8.x4.shared.b16 {%0,%1,%2,%3}, [%4];"
                 : "=r"(r0), "=r"(r1), "=r"(r2), "=r"(r3) : "r"(addr));
}

__device__ __forceinline__ void ldsm4t(uint32_t& r0, uint32_t& r1, uint32_t& r2,
                                       uint32_t& r3, uint32_t addr) {
    asm volatile("ldmatrix.sync.aligned.m8n8.x4.trans.shared.b16 {%0,%1,%2,%3}, [%4];"
                 : "=r"(r0), "=r"(r1), "=r"(r2), "=r"(r3) : "r"(addr));
}

__device__ __forceinline__ void mma_bf16(float c[4], const uint32_t a[4],
                                         const uint32_t b[2]) {
    asm volatile("mma.sync.aligned.m16n8k16.row.col.f32.bf16.bf16.f32 "
                 "{%0,%1,%2,%3}, {%4,%5,%6,%7}, {%8,%9}, {%0,%1,%2,%3};"
                 : "+f"(c[0]), "+f"(c[1]), "+f"(c[2]), "+f"(c[3])
                 : "r"(a[0]), "r"(a[1]), "r"(a[2]), "r"(a[3]),
                   "r"(b[0]), "r"(b[1]));
}

#define ROWB 144          // 72 bf16 per padded row
#define ARR  9216         // one 64x72 bf16 array
#define BOFF 55296        // B side base (6 A arrays)

// ---------------------------------------------------------------------------
// K1: symmetric scores via Karatsuba split-MMA.  64x64 tiles, J >= I only,
// mirror-write for J > I.  K = Dh = 64.
// Per side 6 arrays: {r_hi, r_lo, i_hi, i_lo, s_hi, s_lo} (s = re+im).
// Groups: g0 = Qr·Kr (ac), g1 = Qi·Ki (bd), g2 = Qs·Ks (s).
// re = (ac - bd)*SCALE ; im = (s - ac - bd)*SCALE.
// ---------------------------------------------------------------------------
#define K1_SMEM 110592

__global__ void __launch_bounds__(256, 2) k1_scores(
    const float* __restrict__ xre, const float* __restrict__ xim)
{
    extern __shared__ char sm_[];
    const uint32_t sb = smem_u32(sm_);
    const int tid = threadIdx.x, wid = tid >> 5, lane = tid & 31;
    const int bh = blockIdx.z, b = bh >> 3, h = bh & 7;

    int t = blockIdx.x, I = 0;
    while (t >= 16 - I) { t -= 16 - I; I++; }
    const int J = I + t;
    const int l0 = I << 6, s0 = J << 6;

    const float* xr = xre + (size_t)b * LL * DD + h * 64;
    const float* xi = xim + (size_t)b * LL * DD + h * 64;

    // Fill A (rows l0..) and B (rows s0..): 64 rows x 32 col-pairs each
    #pragma unroll
    for (int i = 0; i < 8; i++) {
        int idx = tid + (i << 8);
        int row = idx >> 5, cp = idx & 31;
        uint32_t off = (uint32_t)(row * ROWB + cp * 4);
        {
            size_t g = (size_t)(l0 + row) * DD + cp * 2;
            float2 fr = *(const float2*)(xr + g);
            float2 fi = *(const float2*)(xi + g);
            uint32_t rh, rl, ih, il, sh, sl;
            split_pack(fr.x, fr.y, rh, rl);
            split_pack(fi.x, fi.y, ih, il);
            split_pack(fr.x + fi.x, fr.y + fi.y, sh, sl);
            *(uint32_t*)(sm_ + 0 * ARR + off) = rh;
            *(uint32_t*)(sm_ + 1 * ARR + off) = rl;
            *(uint32_t*)(sm_ + 2 * ARR + off) = ih;
            *(uint32_t*)(sm_ + 3 * ARR + off) = il;
            *(uint32_t*)(sm_ + 4 * ARR + off) = sh;
            *(uint32_t*)(sm_ + 5 * ARR + off) = sl;
        }
        {
            size_t g = (size_t)(s0 + row) * DD + cp * 2;
            float2 fr = *(const float2*)(xr + g);
            float2 fi = *(const float2*)(xi + g);
            uint32_t rh, rl, ih, il, sh, sl;
            split_pack(fr.x, fr.y, rh, rl);
            split_pack(fi.x, fi.y, ih, il);
            split_pack(fr.x + fi.x, fr.y + fi.y, sh, sl);
            *(uint32_t*)(sm_ + BOFF + 0 * ARR + off) = rh;
            *(uint32_t*)(sm_ + BOFF + 1 * ARR + off) = rl;
            *(uint32_t*)(sm_ + BOFF + 2 * ARR + off) = ih;
            *(uint32_t*)(sm_ + BOFF + 3 * ARR + off) = il;
            *(uint32_t*)(sm_ + BOFF + 4 * ARR + off) = sh;
            *(uint32_t*)(sm_ + BOFF + 5 * ARR + off) = sl;
        }
    }
    __syncthreads();

    const int m0 = (wid >> 2) * 32, n0 = (wid & 3) * 16;
    float acc[3][2][2][4];
    #pragma unroll
    for (int g = 0; g < 3; g++)
        #pragma unroll
        for (int mt = 0; mt < 2; mt++)
            #pragma unroll
            for (int nt = 0; nt < 2; nt++)
                #pragma unroll
                for (int j = 0; j < 4; j++) acc[g][mt][nt][j] = 0.f;

    #pragma unroll
    for (int k0 = 0; k0 < 64; k0 += 16) {
        #pragma unroll
        for (int g = 0; g < 3; g++) {
            uint32_t ah[2][4], al[2][4];
            #pragma unroll
            for (int mt = 0; mt < 2; mt++) {
                uint32_t ad = sb + (2 * g) * ARR +
                    (uint32_t)((m0 + mt * 16 + (lane & 15)) * ROWB +
                               (k0 + ((lane >> 4) << 3)) * 2);
                ldsm4(ah[mt][0], ah[mt][1], ah[mt][2], ah[mt][3], ad);
                ldsm4(al[mt][0], al[mt][1], al[mt][2], al[mt][3], ad + ARR);
            }
            uint32_t bh4[4], bl4[4];
            {
                uint32_t ad = sb + BOFF + (2 * g) * ARR +
                    (uint32_t)((n0 + ((lane >> 4) << 3) + (lane & 7)) * ROWB +
                               (k0 + (((lane >> 3) & 1) << 3)) * 2);
                ldsm4(bh4[0], bh4[1], bh4[2], bh4[3], ad);
                ldsm4(bl4[0], bl4[1], bl4[2], bl4[3], ad + ARR);
            }
            #pragma unroll
            for (int mt = 0; mt < 2; mt++)
                #pragma unroll
                for (int nt = 0; nt < 2; nt++) {
                    uint32_t bh2[2] = { bh4[2 * nt], bh4[2 * nt + 1] };
                    uint32_t bl2[2] = { bl4[2 * nt], bl4[2 * nt + 1] };
                    mma_bf16(acc[g][mt][nt], ah[mt], bh2);
                    mma_bf16(acc[g][mt][nt], ah[mt], bl2);
                    mma_bf16(acc[g][mt][nt], al[mt], bh2);
                }
        }
    }
    __syncthreads();

    // Stage + write (re pass, then im pass).  stage: 64 x 65 floats (16.6KB).
    float* stage = (float*)sm_;
    #pragma unroll
    for (int pass = 0; pass < 2; pass++) {
        #pragma unroll
        for (int mt = 0; mt < 2; mt++)
            #pragma unroll
            for (int nt = 0; nt < 2; nt++) {
                int row = m0 + mt * 16 + (lane >> 2);
                int col = n0 + nt * 8 + ((lane & 3) << 1);
                #pragma unroll
                for (int j = 0; j < 4; j++) {
                    float ac = acc[0][mt][nt][j], bd = acc[1][mt][nt][j];
                    float v = pass ? (acc[2][mt][nt][j] - ac - bd) * SCALE
                                   : (ac - bd) * SCALE;
                    stage[(row + (j >> 1) * 8) * 65 + col + (j & 1)] = v;
                }
            }
        __syncthreads();
        float* gd = pass ? g_sim : g_sre;
        #pragma unroll
        for (int i = 0; i < 16; i++) {
            int idx = tid + (i << 8);
            int r = idx >> 6, c = idx & 63;
            gd[((size_t)bh * LL + l0 + r) * SS + s0 + c] = stage[r * 65 + c];
        }
        if (J > I) {
            #pragma unroll
            for (int i = 0; i < 16; i++) {
                int idx = tid + (i << 8);
                int r = idx >> 6, c = idx & 63;
                gd[((size_t)bh * LL + s0 + r) * SS + l0 + c] = stage[c * 65 + r];
            }
        }
        __syncthreads();
    }
}

// ---------------------------------------------------------------------------
// K2: warp-per-head softmax + head-mean.  Emits bf16 split prob pairs.
// ---------------------------------------------------------------------------
__global__ void __launch_bounds__(256) k_softmax(float* __restrict__ out)
{
    extern __shared__ float psm[];      // pr[8][1024] | pi[8][1024]
    float* pr = psm;
    float* pi = psm + 8 * 1024;

    const int bl = blockIdx.x;
    const int tid = threadIdx.x;
    const int w = tid >> 5, ln = tid & 31;
    const int b = bl >> 10, l = bl & 1023;

    {
        const size_t base = (((size_t)(b * HH + w)) * LL + l) * SS;
        float4 vr[8], vi[8];
        #pragma unroll
        for (int j = 0; j < 8; j++) {
            size_t off = base + (size_t)(j * 128 + (ln << 2));
            vr[j] = *(const float4*)(g_sre + off);
            vi[j] = *(const float4*)(g_sim + off);
        }
        float mr = -3.4e38f, mi = -3.4e38f;
        #pragma unroll
        for (int j = 0; j < 8; j++) {
            mr = fmaxf(mr, fmaxf(fmaxf(vr[j].x, vr[j].y), fmaxf(vr[j].z, vr[j].w)));
            mi = fmaxf(mi, fmaxf(fmaxf(vi[j].x, vi[j].y), fmaxf(vi[j].z, vi[j].w)));
        }
        #pragma unroll
        for (int o = 16; o; o >>= 1) {
            mr = fmaxf(mr, __shfl_xor_sync(0xffffffffu, mr, o));
            mi = fmaxf(mi, __shfl_xor_sync(0xffffffffu, mi, o));
        }
        float sr = 0.f, si = 0.f;
        #pragma unroll
        for (int j = 0; j < 8; j++) {
            vr[j].x = __expf(vr[j].x - mr); vr[j].y = __expf(vr[j].y - mr);
            vr[j].z = __expf(vr[j].z - mr); vr[j].w = __expf(vr[j].w - mr);
            vi[j].x = __expf(vi[j].x - mi); vi[j].y = __expf(vi[j].y - mi);
            vi[j].z = __expf(vi[j].z - mi); vi[j].w = __expf(vi[j].w - mi);
            sr += vr[j].x + vr[j].y + vr[j].z + vr[j].w;
            si += vi[j].x + vi[j].y + vi[j].z + vi[j].w;
        }
        #pragma unroll
        for (int o = 16; o; o >>= 1) {
            sr += __shfl_xor_sync(0xffffffffu, sr, o);
            si += __shfl_xor_sync(0xffffffffu, si, o);
        }
        const float inr = 1.0f / sr, ini = 1.0f / si;
        #pragma unroll
        for (int j = 0; j < 8; j++) {
            vr[j].x *= inr; vr[j].y *= inr; vr[j].z *= inr; vr[j].w *= inr;
            vi[j].x *= ini; vi[j].y *= ini; vi[j].z *= ini; vi[j].w *= ini;
            size_t off = base + (size_t)(j * 128 + (ln << 2));
            uint32_t h01, l01, h23, l23;
            split_pack(vr[j].x, vr[j].y, h01, l01);
            split_pack(vr[j].z, vr[j].w, h23, l23);
            *(uint32_t*)(g_p0r + off)     = h01;
            *(uint32_t*)(g_p0r + off + 2) = h23;
            *(uint32_t*)(g_p1r + off)     = l01;
            *(uint32_t*)(g_p1r + off + 2) = l23;
            split_pack(vi[j].x, vi[j].y, h01, l01);
            split_pack(vi[j].z, vi[j].w, h23, l23);
            *(uint32_t*)(g_p0i + off)     = h01;
            *(uint32_t*)(g_p0i + off + 2) = h23;
            *(uint32_t*)(g_p1i + off)     = l01;
            *(uint32_t*)(g_p1i + off + 2) = l23;
            int so = w * 1024 + j * 128 + (ln << 2);
            *(float4*)(pr + so) = vr[j];
            *(float4*)(pi + so) = vi[j];
        }
    }
    __syncthreads();

    float4 ar = make_float4(0.f, 0.f, 0.f, 0.f);
    float4 ai = make_float4(0.f, 0.f, 0.f, 0.f);
    #pragma unroll
    for (int hh = 0; hh < HH; hh++) {
        float4 r = *(const float4*)(pr + hh * 1024 + (tid << 2));
        float4 m = *(const float4*)(pi + hh * 1024 + (tid << 2));
        ar.x += r.x; ar.y += r.y; ar.z += r.z; ar.w += r.w;
        ai.x += m.x; ai.y += m.y; ai.z += m.z; ai.w += m.w;
    }
    const float wgt = 1.0f / (float)HH;
    ar.x *= wgt; ar.y *= wgt; ar.z *= wgt; ar.w *= wgt;
    ai.x *= wgt; ai.y *= wgt; ai.z *= wgt; ai.w *= wgt;
    size_t ao = (size_t)bl * SS + ((size_t)tid << 2);
    *(float4*)(out + ATTN_RE_OFF + ao) = ar;
    *(float4*)(out + ATTN_IM_OFF + ao) = ai;
}

// ---------------------------------------------------------------------------
// K3: output via Karatsuba split-MMA.  CTA tile 64(l) x 64(d), K = S = 1024
// in 16 chunks of 64.  A arrays: {Ar_hi, Ar_lo, Ai_hi, Ai_lo, As_hi, As_lo}
// (As = Ar+Ai computed locally).  B (V, [s][d] layout): same 6-array scheme.
// o_re = ac - bd ; o_im = s - ac - bd.
// ---------------------------------------------------------------------------
#define K3_SMEM 110592

__global__ void __launch_bounds__(256, 2) k3_out(
    const float* __restrict__ xre, const float* __restrict__ xim,
    float* __restrict__ out)
{
    extern __shared__ char sm_[];
    const uint32_t sb = smem_u32(sm_);
    const int tid = threadIdx.x, wid = tid >> 5, lane = tid & 31;
    const int bh = blockIdx.y, b = bh >> 3, h = bh & 7;
    const int l0 = blockIdx.x << 6;

    const float* xr = xre + (size_t)b * LL * DD + h * 64;
    const float* xi = xim + (size_t)b * LL * DD + h * 64;
    const size_t abase = (size_t)bh * LL + l0;

    const int m0 = (wid >> 2) * 32, n0 = (wid & 3) * 16;
    float acc[3][2][2][4];
    #pragma unroll
    for (int g = 0; g < 3; g++)
        #pragma unroll
        for (int mt = 0; mt < 2; mt++)
            #pragma unroll
            for (int nt = 0; nt < 2; nt++)
                #pragma unroll
                for (int j = 0; j < 4; j++) acc[g][mt][nt][j] = 0.f;

    for (int c = 0; c < 16; c++) {
        if (c) __syncthreads();
        // Fill A: 64 l-rows x 32 s-pairs; sums computed locally
        #pragma unroll
        for (int i = 0; i < 8; i++) {
            int idx = tid + (i << 8);
            int row = idx >> 5, cp = idx & 31;
            size_t gofs = (abase + row) * SS + c * 64 + cp * 2;
            uint32_t w0 = *(const uint32_t*)(g_p0r + gofs);
            uint32_t w1 = *(const uint32_t*)(g_p1r + gofs);
            uint32_t w2 = *(const uint32_t*)(g_p0i + gofs);
            uint32_t w3 = *(const uint32_t*)(g_p1i + gofs);
            float2 f0 = bf2_to_f2(w0), f1 = bf2_to_f2(w1);
            float2 f2 = bf2_to_f2(w2), f3 = bf2_to_f2(w3);
            uint32_t sh, sl;
            split_pack((f0.x + f1.x) + (f2.x + f3.x),
                       (f0.y + f1.y) + (f2.y + f3.y), sh, sl);
            uint32_t off = (uint32_t)(row * ROWB + cp * 4);
            *(uint32_t*)(sm_ + 0 * ARR + off) = w0;
            *(uint32_t*)(sm_ + 1 * ARR + off) = w1;
            *(uint32_t*)(sm_ + 2 * ARR + off) = w2;
            *(uint32_t*)(sm_ + 3 * ARR + off) = w3;
            *(uint32_t*)(sm_ + 4 * ARR + off) = sh;
            *(uint32_t*)(sm_ + 5 * ARR + off) = sl;
        }
        // Fill V: 64 s-rows x 32 d-pairs, [s][d] layout, split + sum on the fly
        #pragma unroll
        for (int i = 0; i < 8; i++) {
            int idx = tid + (i << 8);
            int row = idx >> 5, cp = idx & 31;
            uint32_t off = (uint32_t)(BOFF + row * ROWB + cp * 4);
            size_t g = (size_t)(c * 64 + row) * DD + cp * 2;
            float2 fr = *(const float2*)(xr + g);
            float2 fi = *(const float2*)(xi + g);
            uint32_t rh, rl, ih, il, sh, sl;
            split_pack(fr.x, fr.y, rh, rl);
            split_pack(fi.x, fi.y, ih, il);
            split_pack(fr.x + fi.x, fr.y + fi.y, sh, sl);
            *(uint32_t*)(sm_ + 0 * ARR + off) = rh;
            *(uint32_t*)(sm_ + 1 * ARR + off) = rl;
            *(uint32_t*)(sm_ + 2 * ARR + off) = ih;
            *(uint32_t*)(sm_ + 3 * ARR + off) = il;
            *(uint32_t*)(sm_ + 4 * ARR + off) = sh;
            *(uint32_t*)(sm_ + 5 * ARR + off) = sl;
        }
        __syncthreads();

        #pragma unroll
        for (int k0 = 0; k0 < 64; k0 += 16) {
            #pragma unroll
            for (int g = 0; g < 3; g++) {
                uint32_t ah[2][4], al[2][4];
                #pragma unroll
                for (int mt = 0; mt < 2; mt++) {
                    uint32_t ad = sb + (2 * g) * ARR +
                        (uint32_t)((m0 + mt * 16 + (lane & 15)) * ROWB +
                                   (k0 + ((lane >> 4) << 3)) * 2);
                    ldsm4(ah[mt][0], ah[mt][1], ah[mt][2], ah[mt][3], ad);
                    ldsm4(al[mt][0], al[mt][1], al[mt][2], al[mt][3], ad + ARR);
                }
                uint32_t bh4[4], bl4[4];
                {
                    uint32_t ad = sb + BOFF + (2 * g) * ARR +
                        (uint32_t)((k0 + (((lane >> 3) & 1) << 3) + (lane & 7)) * ROWB +
                                   (n0 + ((lane >> 4) << 3)) * 2);
                    ldsm4t(bh4[0], bh4[1], bh4[2], bh4[3], ad);
                    ldsm4t(bl4[0], bl4[1], bl4[2], bl4[3], ad + ARR);
                }
                #pragma unroll
                for (int mt = 0; mt < 2; mt++)
                    #pragma unroll
                    for (int nt = 0; nt < 2; nt++) {
                        uint32_t bh2[2] = { bh4[2 * nt], bh4[2 * nt + 1] };
                        uint32_t bl2[2] = { bl4[2 * nt], bl4[2 * nt + 1] };
                        mma_bf16(acc[g][mt][nt], ah[mt], bh2);
                        mma_bf16(acc[g][mt][nt], ah[mt], bl2);
                        mma_bf16(acc[g][mt][nt], al[mt], bh2);
                    }
            }
        }
    }

    // Epilogue: direct float2 stores
    #pragma unroll
    for (int mt = 0; mt < 2; mt++)
        #pragma unroll
        for (int nt = 0; nt < 2; nt++) {
            int row = l0 + m0 + mt * 16 + (lane >> 2);
            int col = h * 64 + n0 + nt * 8 + ((lane & 3) << 1);
            size_t base = ((size_t)b * LL + row) * DD + col;
            float* ac = acc[0][mt][nt];
            float* bd = acc[1][mt][nt];
            float* s  = acc[2][mt][nt];
            *(float2*)(out + OUT_RE_OFF + base) =
                make_float2(ac[0] - bd[0], ac[1] - bd[1]);
            *(float2*)(out + OUT_RE_OFF + base + 8 * DD) =
                make_float2(ac[2] - bd[2], ac[3] - bd[3]);
            *(float2*)(out + OUT_IM_OFF + base) =
                make_float2(s[0] - ac[0] - bd[0], s[1] - ac[1] - bd[1]);
            *(float2*)(out + OUT_IM_OFF + base + 8 * DD) =
                make_float2(s[2] - ac[2] - bd[2], s[3] - ac[3] - bd[3]);
        }
}

// ---------------------------------------------------------------------------
extern "C" void kernel_launch(void* const* d_in, const int* in_sizes, int n_in,
                              void* d_out, int out_size)
{
    const float* xre = (const float*)d_in[0];
    const float* xim = (const float*)d_in[1];
    float* outp = (float*)d_out;

    const int smem2 = 2 * 8 * 1024 * 4;  // 65536
    cudaFuncSetAttribute(k1_scores, cudaFuncAttributeMaxDynamicSharedMemorySize, K1_SMEM);
    cudaFuncSetAttribute(k_softmax, cudaFuncAttributeMaxDynamicSharedMemorySize, smem2);
    cudaFuncSetAttribute(k3_out,    cudaFuncAttributeMaxDynamicSharedMemorySize, K3_SMEM);

    k1_scores<<<dim3(136, 1, 64), 256, K1_SMEM>>>(xre, xim);
    k_softmax<<<BB * LL, 256, smem2>>>(outp);
    k3_out<<<dim3(16, 64), 256, K3_SMEM>>>(xre, xim, outp);
}

// round 12
// speedup vs baseline: 2.4883x; 1.0068x over previous
#include <cuda_runtime.h>
#include <cuda_bf16.h>
#include <math.h>
#include <stdint.h>

// Problem constants
#define BB 8
#define LL 1024
#define DD 512
#define HH 8
#define SS 1024
#define SCALE 0.125f

// Output sections (floats): out_re | out_im | attn_re | attn_im
#define OUT_RE_OFF  0UL
#define OUT_IM_OFF  4194304UL
#define ATTN_RE_OFF 8388608UL
#define ATTN_IM_OFF 16777216UL

// Scratch
__device__ float g_sre[(size_t)BB * HH * LL * SS];           // scaled scores re
__device__ float g_sim[(size_t)BB * HH * LL * SS];           // scaled scores im
__device__ __nv_bfloat16 g_p0r[(size_t)BB * HH * LL * SS];   // prob splits
__device__ __nv_bfloat16 g_p1r[(size_t)BB * HH * LL * SS];
__device__ __nv_bfloat16 g_p0i[(size_t)BB * HH * LL * SS];
__device__ __nv_bfloat16 g_p1i[(size_t)BB * HH * LL * SS];

// Pre-split input: 6 bf16 arrays [B, L, D] (r_hi, r_lo, i_hi, i_lo, s_hi, s_lo)
#define XN ((size_t)BB * LL * DD)
__device__ __nv_bfloat16 g_xrh[XN], g_xrl[XN];
__device__ __nv_bfloat16 g_xih[XN], g_xil[XN];
__device__ __nv_bfloat16 g_xsh[XN], g_xsl[XN];

// ---------------------------------------------------------------------------
// Helpers (plain sm_80+ PTX only)
// ---------------------------------------------------------------------------
__device__ __forceinline__ uint32_t smem_u32(const void* p) {
    uint32_t a;
    asm("{ .reg .u64 t; cvta.to.shared.u64 t, %1; cvt.u32.u64 %0, t; }"
        : "=r"(a) : "l"(p));
    return a;
}

__device__ __forceinline__ uint32_t pack_bf(__nv_bfloat16 a, __nv_bfloat16 b) {
    __nv_bfloat162 t(a, b);
    return *reinterpret_cast<uint32_t*>(&t);
}

__device__ __forceinline__ void split_pack(float f0, float f1, uint32_t& hi, uint32_t& lo) {
    __nv_bfloat16 h0 = __float2bfloat16(f0), h1 = __float2bfloat16(f1);
    float r0 = f0 - __bfloat162float(h0), r1 = f1 - __bfloat162float(h1);
    hi = pack_bf(h0, h1);
    lo = pack_bf(__float2bfloat16(r0), __float2bfloat16(r1));
}

__device__ __forceinline__ float2 bf2_to_f2(uint32_t w) {
    __nv_bfloat162 t = *reinterpret_cast<__nv_bfloat162*>(&w);
    return make_float2(__low2float(t), __high2float(t));
}

__device__ __forceinline__ void ldsm4(uint32_t& r0, uint32_t& r1, uint32_t& r2,
                                      uint32_t& r3, uint32_t addr) {
    asm volatile("ldmatrix.sync.aligned.m8n8.x4.shared.b16 {%0,%1,%2,%3}, [%4];"
                 : "=r"(r0), "=r"(r1), "=r"(r2), "=r"(r3) : "r"(addr));
}

__device__ __forceinline__ void ldsm4t(uint32_t& r0, uint32_t& r1, uint32_t& r2,
                                       uint32_t& r3, uint32_t addr) {
    asm volatile("ldmatrix.sync.aligned.m8n8.x4.trans.shared.b16 {%0,%1,%2,%3}, [%4];"
                 : "=r"(r0), "=r"(r1), "=r"(r2), "=r"(r3) : "r"(addr));
}

__device__ __forceinline__ void mma_bf16(float c[4], const uint32_t a[4],
                                         const uint32_t b[2]) {
    asm volatile("mma.sync.aligned.m16n8k16.row.col.f32.bf16.bf16.f32 "
                 "{%0,%1,%2,%3}, {%4,%5,%6,%7}, {%8,%9}, {%0,%1,%2,%3};"
                 : "+f"(c[0]), "+f"(c[1]), "+f"(c[2]), "+f"(c[3])
                 : "r"(a[0]), "r"(a[1]), "r"(a[2]), "r"(a[3]),
                   "r"(b[0]), "r"(b[1]));
}

#define ROWB 144          // 72 bf16 per padded row
#define ARR  9216         // one 64x72 bf16 array
#define BOFF 55296        // B side base (6 A arrays)

// ---------------------------------------------------------------------------
// K0: pre-split x into 6 bf16 arrays.  Each thread handles 8 elements.
// ---------------------------------------------------------------------------
__global__ void __launch_bounds__(256) k0_split(
    const float* __restrict__ xre, const float* __restrict__ xim)
{
    const size_t base = ((size_t)blockIdx.x * 256 + threadIdx.x) * 8;
    float4 r0 = *(const float4*)(xre + base);
    float4 r1 = *(const float4*)(xre + base + 4);
    float4 i0 = *(const float4*)(xim + base);
    float4 i1 = *(const float4*)(xim + base + 4);
    float fr[8] = { r0.x, r0.y, r0.z, r0.w, r1.x, r1.y, r1.z, r1.w };
    float fi[8] = { i0.x, i0.y, i0.z, i0.w, i1.x, i1.y, i1.z, i1.w };
    uint32_t rh[4], rl[4], ih[4], il[4], sh[4], sl[4];
    #pragma unroll
    for (int j = 0; j < 4; j++) {
        split_pack(fr[2 * j], fr[2 * j + 1], rh[j], rl[j]);
        split_pack(fi[2 * j], fi[2 * j + 1], ih[j], il[j]);
        split_pack(fr[2 * j] + fi[2 * j], fr[2 * j + 1] + fi[2 * j + 1], sh[j], sl[j]);
    }
    *(uint4*)(g_xrh + base) = make_uint4(rh[0], rh[1], rh[2], rh[3]);
    *(uint4*)(g_xrl + base) = make_uint4(rl[0], rl[1], rl[2], rl[3]);
    *(uint4*)(g_xih + base) = make_uint4(ih[0], ih[1], ih[2], ih[3]);
    *(uint4*)(g_xil + base) = make_uint4(il[0], il[1], il[2], il[3]);
    *(uint4*)(g_xsh + base) = make_uint4(sh[0], sh[1], sh[2], sh[3]);
    *(uint4*)(g_xsl + base) = make_uint4(sl[0], sl[1], sl[2], sl[3]);
}

// ---------------------------------------------------------------------------
// K1: symmetric scores via Karatsuba split-MMA.  64x64 tiles, J >= I only,
// mirror-write for J > I.  Fills are pure uint4 copies from pre-split arrays.
// re = (ac - bd)*SCALE ; im = (s - ac - bd)*SCALE.
// ---------------------------------------------------------------------------
#define K1_SMEM 110592

__global__ void __launch_bounds__(256, 2) k1_scores(int dummy)
{
    extern __shared__ char sm_[];
    const uint32_t sb = smem_u32(sm_);
    const int tid = threadIdx.x, wid = tid >> 5, lane = tid & 31;
    const int bh = blockIdx.z, b = bh >> 3, h = bh & 7;

    int t = blockIdx.x, I = 0;
    while (t >= 16 - I) { t -= 16 - I; I++; }
    const int J = I + t;
    const int l0 = I << 6, s0 = J << 6;

    const size_t xbase = (size_t)b * LL * DD + h * 64;
    const __nv_bfloat16* xarr[6] = { g_xrh, g_xrl, g_xih, g_xil, g_xsh, g_xsl };

    // Fill A (rows l0..) and B (rows s0..): 64 rows x 8 qwords, 6 arrays each
    #pragma unroll
    for (int i = 0; i < 2; i++) {
        int idx = tid + (i << 8);
        int row = idx >> 3, q = idx & 7;
        uint32_t off = (uint32_t)(row * ROWB + q * 16);
        size_t ga = xbase + (size_t)(l0 + row) * DD + q * 8;
        size_t gb = xbase + (size_t)(s0 + row) * DD + q * 8;
        #pragma unroll
        for (int arr = 0; arr < 6; arr++) {
            *(uint4*)(sm_ + arr * ARR + off)        = *(const uint4*)(xarr[arr] + ga);
            *(uint4*)(sm_ + BOFF + arr * ARR + off) = *(const uint4*)(xarr[arr] + gb);
        }
    }
    __syncthreads();

    const int m0 = (wid >> 2) * 32, n0 = (wid & 3) * 16;
    float acc[3][2][2][4];
    #pragma unroll
    for (int g = 0; g < 3; g++)
        #pragma unroll
        for (int mt = 0; mt < 2; mt++)
            #pragma unroll
            for (int nt = 0; nt < 2; nt++)
                #pragma unroll
                for (int j = 0; j < 4; j++) acc[g][mt][nt][j] = 0.f;

    #pragma unroll
    for (int k0 = 0; k0 < 64; k0 += 16) {
        #pragma unroll
        for (int g = 0; g < 3; g++) {
            uint32_t ah[2][4], al[2][4];
            #pragma unroll
            for (int mt = 0; mt < 2; mt++) {
                uint32_t ad = sb + (2 * g) * ARR +
                    (uint32_t)((m0 + mt * 16 + (lane & 15)) * ROWB +
                               (k0 + ((lane >> 4) << 3)) * 2);
                ldsm4(ah[mt][0], ah[mt][1], ah[mt][2], ah[mt][3], ad);
                ldsm4(al[mt][0], al[mt][1], al[mt][2], al[mt][3], ad + ARR);
            }
            uint32_t bh4[4], bl4[4];
            {
                uint32_t ad = sb + BOFF + (2 * g) * ARR +
                    (uint32_t)((n0 + ((lane >> 4) << 3) + (lane & 7)) * ROWB +
                               (k0 + (((lane >> 3) & 1) << 3)) * 2);
                ldsm4(bh4[0], bh4[1], bh4[2], bh4[3], ad);
                ldsm4(bl4[0], bl4[1], bl4[2], bl4[3], ad + ARR);
            }
            #pragma unroll
            for (int mt = 0; mt < 2; mt++)
                #pragma unroll
                for (int nt = 0; nt < 2; nt++) {
                    uint32_t bh2[2] = { bh4[2 * nt], bh4[2 * nt + 1] };
                    uint32_t bl2[2] = { bl4[2 * nt], bl4[2 * nt + 1] };
                    mma_bf16(acc[g][mt][nt], ah[mt], bh2);
                    mma_bf16(acc[g][mt][nt], ah[mt], bl2);
                    mma_bf16(acc[g][mt][nt], al[mt], bh2);
                }
        }
    }
    __syncthreads();

    // Single-pass staging: re @ 0, im @ 16640 (64 x 65 floats each)
    float* stre = (float*)sm_;
    float* stim = (float*)(sm_ + 16640);
    #pragma unroll
    for (int mt = 0; mt < 2; mt++)
        #pragma unroll
        for (int nt = 0; nt < 2; nt++) {
            int row = m0 + mt * 16 + (lane >> 2);
            int col = n0 + nt * 8 + ((lane & 3) << 1);
            #pragma unroll
            for (int j = 0; j < 4; j++) {
                float ac = acc[0][mt][nt][j], bd = acc[1][mt][nt][j];
                int so = (row + (j >> 1) * 8) * 65 + col + (j & 1);
                stre[so] = (ac - bd) * SCALE;
                stim[so] = (acc[2][mt][nt][j] - ac - bd) * SCALE;
            }
        }
    __syncthreads();

    #pragma unroll
    for (int i = 0; i < 16; i++) {
        int idx = tid + (i << 8);
        int r = idx >> 6, c = idx & 63;
        g_sre[((size_t)bh * LL + l0 + r) * SS + s0 + c] = stre[r * 65 + c];
        g_sim[((size_t)bh * LL + l0 + r) * SS + s0 + c] = stim[r * 65 + c];
    }
    if (J > I) {
        #pragma unroll
        for (int i = 0; i < 16; i++) {
            int idx = tid + (i << 8);
            int r = idx >> 6, c = idx & 63;
            g_sre[((size_t)bh * LL + s0 + r) * SS + l0 + c] = stre[c * 65 + r];
            g_sim[((size_t)bh * LL + s0 + r) * SS + l0 + c] = stim[c * 65 + r];
        }
    }
}

// ---------------------------------------------------------------------------
// K2: warp-per-head softmax + head-mean.  Emits bf16 split prob pairs.
// ---------------------------------------------------------------------------
__global__ void __launch_bounds__(256) k_softmax(float* __restrict__ out)
{
    extern __shared__ float psm[];      // pr[8][1024] | pi[8][1024]
    float* pr = psm;
    float* pi = psm + 8 * 1024;

    const int bl = blockIdx.x;
    const int tid = threadIdx.x;
    const int w = tid >> 5, ln = tid & 31;
    const int b = bl >> 10, l = bl & 1023;

    {
        const size_t base = (((size_t)(b * HH + w)) * LL + l) * SS;
        float4 vr[8], vi[8];
        #pragma unroll
        for (int j = 0; j < 8; j++) {
            size_t off = base + (size_t)(j * 128 + (ln << 2));
            vr[j] = *(const float4*)(g_sre + off);
            vi[j] = *(const float4*)(g_sim + off);
        }
        float mr = -3.4e38f, mi = -3.4e38f;
        #pragma unroll
        for (int j = 0; j < 8; j++) {
            mr = fmaxf(mr, fmaxf(fmaxf(vr[j].x, vr[j].y), fmaxf(vr[j].z, vr[j].w)));
            mi = fmaxf(mi, fmaxf(fmaxf(vi[j].x, vi[j].y), fmaxf(vi[j].z, vi[j].w)));
        }
        #pragma unroll
        for (int o = 16; o; o >>= 1) {
            mr = fmaxf(mr, __shfl_xor_sync(0xffffffffu, mr, o));
            mi = fmaxf(mi, __shfl_xor_sync(0xffffffffu, mi, o));
        }
        float sr = 0.f, si = 0.f;
        #pragma unroll
        for (int j = 0; j < 8; j++) {
            vr[j].x = __expf(vr[j].x - mr); vr[j].y = __expf(vr[j].y - mr);
            vr[j].z = __expf(vr[j].z - mr); vr[j].w = __expf(vr[j].w - mr);
            vi[j].x = __expf(vi[j].x - mi); vi[j].y = __expf(vi[j].y - mi);
            vi[j].z = __expf(vi[j].z - mi); vi[j].w = __expf(vi[j].w - mi);
            sr += vr[j].x + vr[j].y + vr[j].z + vr[j].w;
            si += vi[j].x + vi[j].y + vi[j].z + vi[j].w;
        }
        #pragma unroll
        for (int o = 16; o; o >>= 1) {
            sr += __shfl_xor_sync(0xffffffffu, sr, o);
            si += __shfl_xor_sync(0xffffffffu, si, o);
        }
        const float inr = 1.0f / sr, ini = 1.0f / si;
        #pragma unroll
        for (int j = 0; j < 8; j++) {
            vr[j].x *= inr; vr[j].y *= inr; vr[j].z *= inr; vr[j].w *= inr;
            vi[j].x *= ini; vi[j].y *= ini; vi[j].z *= ini; vi[j].w *= ini;
            size_t off = base + (size_t)(j * 128 + (ln << 2));
            uint32_t h01, l01, h23, l23;
            split_pack(vr[j].x, vr[j].y, h01, l01);
            split_pack(vr[j].z, vr[j].w, h23, l23);
            *(uint32_t*)(g_p0r + off)     = h01;
            *(uint32_t*)(g_p0r + off + 2) = h23;
            *(uint32_t*)(g_p1r + off)     = l01;
            *(uint32_t*)(g_p1r + off + 2) = l23;
            split_pack(vi[j].x, vi[j].y, h01, l01);
            split_pack(vi[j].z, vi[j].w, h23, l23);
            *(uint32_t*)(g_p0i + off)     = h01;
            *(uint32_t*)(g_p0i + off + 2) = h23;
            *(uint32_t*)(g_p1i + off)     = l01;
            *(uint32_t*)(g_p1i + off + 2) = l23;
            int so = w * 1024 + j * 128 + (ln << 2);
            *(float4*)(pr + so) = vr[j];
            *(float4*)(pi + so) = vi[j];
        }
    }
    __syncthreads();

    float4 ar = make_float4(0.f, 0.f, 0.f, 0.f);
    float4 ai = make_float4(0.f, 0.f, 0.f, 0.f);
    #pragma unroll
    for (int hh = 0; hh < HH; hh++) {
        float4 r = *(const float4*)(pr + hh * 1024 + (tid << 2));
        float4 m = *(const float4*)(pi + hh * 1024 + (tid << 2));
        ar.x += r.x; ar.y += r.y; ar.z += r.z; ar.w += r.w;
        ai.x += m.x; ai.y += m.y; ai.z += m.z; ai.w += m.w;
    }
    const float wgt = 1.0f / (float)HH;
    ar.x *= wgt; ar.y *= wgt; ar.z *= wgt; ar.w *= wgt;
    ai.x *= wgt; ai.y *= wgt; ai.z *= wgt; ai.w *= wgt;
    size_t ao = (size_t)bl * SS + ((size_t)tid << 2);
    *(float4*)(out + ATTN_RE_OFF + ao) = ar;
    *(float4*)(out + ATTN_IM_OFF + ao) = ai;
}

// ---------------------------------------------------------------------------
// K3: output via Karatsuba split-MMA.  CTA tile 64(l) x 64(d), K = S = 1024
// in 16 chunks of 64.  A: prob splits (copies) + local sum splits;
// B (V, [s][d]): pure copies from pre-split arrays.
// o_re = ac - bd ; o_im = s - ac - bd.
// ---------------------------------------------------------------------------
#define K3_SMEM 110592

__global__ void __launch_bounds__(256, 2) k3_out(float* __restrict__ out)
{
    extern __shared__ char sm_[];
    const uint32_t sb = smem_u32(sm_);
    const int tid = threadIdx.x, wid = tid >> 5, lane = tid & 31;
    const int bh = blockIdx.y, b = bh >> 3, h = bh & 7;
    const int l0 = blockIdx.x << 6;

    const size_t xbase = (size_t)b * LL * DD + h * 64;
    const __nv_bfloat16* xarr[6] = { g_xrh, g_xrl, g_xih, g_xil, g_xsh, g_xsl };
    const size_t abase = (size_t)bh * LL + l0;

    const int m0 = (wid >> 2) * 32, n0 = (wid & 3) * 16;
    float acc[3][2][2][4];
    #pragma unroll
    for (int g = 0; g < 3; g++)
        #pragma unroll
        for (int mt = 0; mt < 2; mt++)
            #pragma unroll
            for (int nt = 0; nt < 2; nt++)
                #pragma unroll
                for (int j = 0; j < 4; j++) acc[g][mt][nt][j] = 0.f;

    for (int c = 0; c < 16; c++) {
        if (c) __syncthreads();
        // Fill A: 64 l-rows x 8 qwords; prob splits copied, sum split locally
        #pragma unroll
        for (int i = 0; i < 2; i++) {
            int idx = tid + (i << 8);
            int row = idx >> 3, q = idx & 7;
            size_t gofs = (abase + row) * SS + c * 64 + q * 8;
            uint4 a0 = *(const uint4*)(g_p0r + gofs);
            uint4 a1 = *(const uint4*)(g_p1r + gofs);
            uint4 a2 = *(const uint4*)(g_p0i + gofs);
            uint4 a3 = *(const uint4*)(g_p1i + gofs);
            uint32_t c0[4] = { a0.x, a0.y, a0.z, a0.w };
            uint32_t c1[4] = { a1.x, a1.y, a1.z, a1.w };
            uint32_t c2[4] = { a2.x, a2.y, a2.z, a2.w };
            uint32_t c3[4] = { a3.x, a3.y, a3.z, a3.w };
            uint32_t sh[4], sl[4];
            #pragma unroll
            for (int j = 0; j < 4; j++) {
                float2 f0 = bf2_to_f2(c0[j]), f1 = bf2_to_f2(c1[j]);
                float2 f2 = bf2_to_f2(c2[j]), f3 = bf2_to_f2(c3[j]);
                split_pack((f0.x + f1.x) + (f2.x + f3.x),
                           (f0.y + f1.y) + (f2.y + f3.y), sh[j], sl[j]);
            }
            uint32_t off = (uint32_t)(row * ROWB + q * 16);
            *(uint4*)(sm_ + 0 * ARR + off) = a0;
            *(uint4*)(sm_ + 1 * ARR + off) = a1;
            *(uint4*)(sm_ + 2 * ARR + off) = a2;
            *(uint4*)(sm_ + 3 * ARR + off) = a3;
            *(uint4*)(sm_ + 4 * ARR + off) = make_uint4(sh[0], sh[1], sh[2], sh[3]);
            *(uint4*)(sm_ + 5 * ARR + off) = make_uint4(sl[0], sl[1], sl[2], sl[3]);
        }
        // Fill V: 64 s-rows x 8 qwords, pure copies from pre-split arrays
        #pragma unroll
        for (int i = 0; i < 2; i++) {
            int idx = tid + (i << 8);
            int row = idx >> 3, q = idx & 7;
            size_t g = xbase + (size_t)(c * 64 + row) * DD + q * 8;
            uint32_t off = (uint32_t)(BOFF + row * ROWB + q * 16);
            #pragma unroll
            for (int arr = 0; arr < 6; arr++)
                *(uint4*)(sm_ + arr * ARR + off) = *(const uint4*)(xarr[arr] + g);
        }
        __syncthreads();

        #pragma unroll
        for (int k0 = 0; k0 < 64; k0 += 16) {
            #pragma unroll
            for (int g = 0; g < 3; g++) {
                uint32_t ah[2][4], al[2][4];
                #pragma unroll
                for (int mt = 0; mt < 2; mt++) {
                    uint32_t ad = sb + (2 * g) * ARR +
                        (uint32_t)((m0 + mt * 16 + (lane & 15)) * ROWB +
                                   (k0 + ((lane >> 4) << 3)) * 2);
                    ldsm4(ah[mt][0], ah[mt][1], ah[mt][2], ah[mt][3], ad);
                    ldsm4(al[mt][0], al[mt][1], al[mt][2], al[mt][3], ad + ARR);
                }
                uint32_t bh4[4], bl4[4];
                {
                    uint32_t ad = sb + BOFF + (2 * g) * ARR +
                        (uint32_t)((k0 + (((lane >> 3) & 1) << 3) + (lane & 7)) * ROWB +
                                   (n0 + ((lane >> 4) << 3)) * 2);
                    ldsm4t(bh4[0], bh4[1], bh4[2], bh4[3], ad);
                    ldsm4t(bl4[0], bl4[1], bl4[2], bl4[3], ad + ARR);
                }
                #pragma unroll
                for (int mt = 0; mt < 2; mt++)
                    #pragma unroll
                    for (int nt = 0; nt < 2; nt++) {
                        uint32_t bh2[2] = { bh4[2 * nt], bh4[2 * nt + 1] };
                        uint32_t bl2[2] = { bl4[2 * nt], bl4[2 * nt + 1] };
                        mma_bf16(acc[g][mt][nt], ah[mt], bh2);
                        mma_bf16(acc[g][mt][nt], ah[mt], bl2);
                        mma_bf16(acc[g][mt][nt], al[mt], bh2);
                    }
            }
        }
    }

    // Epilogue: direct float2 stores
    #pragma unroll
    for (int mt = 0; mt < 2; mt++)
        #pragma unroll
        for (int nt = 0; nt < 2; nt++) {
            int row = l0 + m0 + mt * 16 + (lane >> 2);
            int col = h * 64 + n0 + nt * 8 + ((lane & 3) << 1);
            size_t base = ((size_t)b * LL + row) * DD + col;
            float* ac = acc[0][mt][nt];
            float* bd = acc[1][mt][nt];
            float* s  = acc[2][mt][nt];
            *(float2*)(out + OUT_RE_OFF + base) =
                make_float2(ac[0] - bd[0], ac[1] - bd[1]);
            *(float2*)(out + OUT_RE_OFF + base + 8 * DD) =
                make_float2(ac[2] - bd[2], ac[3] - bd[3]);
            *(float2*)(out + OUT_IM_OFF + base) =
                make_float2(s[0] - ac[0] - bd[0], s[1] - ac[1] - bd[1]);
            *(float2*)(out + OUT_IM_OFF + base + 8 * DD) =
                make_float2(s[2] - ac[2] - bd[2], s[3] - ac[3] - bd[3]);
        }
}

// ---------------------------------------------------------------------------
extern "C" void kernel_launch(void* const* d_in, const int* in_sizes, int n_in,
                              void* d_out, int out_size)
{
    const float* xre = (const float*)d_in[0];
    const float* xim = (const float*)d_in[1];
    float* outp = (float*)d_out;

    const int smem2 = 2 * 8 * 1024 * 4;  // 65536
    cudaFuncSetAttribute(k1_scores, cudaFuncAttributeMaxDynamicSharedMemorySize, K1_SMEM);
    cudaFuncSetAttribute(k_softmax, cudaFuncAttributeMaxDynamicSharedMemorySize, smem2);
    cudaFuncSetAttribute(k3_out,    cudaFuncAttributeMaxDynamicSharedMemorySize, K3_SMEM);

    k0_split<<<2048, 256>>>(xre, xim);
    k1_scores<<<dim3(136, 1, 64), 256, K1_SMEM>>>(0);
    k_softmax<<<BB * LL, 256, smem2>>>(outp);
    k3_out<<<dim3(16, 64), 256, K3_SMEM>>>(outp);
}